// round 5
// baseline (speedup 1.0000x reference)
#include <cuda_runtime.h>
#include <cuda_bf16.h>
#include <math.h>
#include <stdint.h>

#define LEN 2048
#define DIM 2048
#define NH 16
#define HD 128
#define SCALE 0.08838834764831845f  /* 1/sqrt(128) */

// ---------------- scratch (allocation-free: __device__ globals) ----------------
__device__ float g_qkv[(size_t)LEN * 3 * DIM];               // [L, 3*DIM] fp32
__device__ float g_s[(size_t)NH * LEN * LEN];                // [H, L, L] logits fp32

__device__ __nv_bfloat16 g_xh[(size_t)LEN * DIM];            // x hi/lo
__device__ __nv_bfloat16 g_xl[(size_t)LEN * DIM];
__device__ __nv_bfloat16 g_wqh[(size_t)3 * DIM * DIM];       // w_qkv hi/lo
__device__ __nv_bfloat16 g_wql[(size_t)3 * DIM * DIM];
__device__ __nv_bfloat16 g_wph[(size_t)DIM * DIM];           // w_proj hi/lo
__device__ __nv_bfloat16 g_wpl[(size_t)DIM * DIM];
__device__ __nv_bfloat16 g_qh[(size_t)NH * LEN * HD];        // q hi/lo [H,L,D]
__device__ __nv_bfloat16 g_ql[(size_t)NH * LEN * HD];
__device__ __nv_bfloat16 g_kh[(size_t)NH * LEN * HD];        // k hi/lo [H,L,D]
__device__ __nv_bfloat16 g_kl[(size_t)NH * LEN * HD];
__device__ __nv_bfloat16 g_vth[(size_t)NH * HD * LEN];       // v^T hi/lo [H,D,L]
__device__ __nv_bfloat16 g_vtl[(size_t)NH * HD * LEN];
__device__ __nv_bfloat16 g_ph[(size_t)NH * LEN * LEN];       // probs hi/lo [H,L,L]
__device__ __nv_bfloat16 g_pl[(size_t)NH * LEN * LEN];
__device__ __nv_bfloat16 g_oh[(size_t)LEN * DIM];            // O hi/lo [L, H*D]
__device__ __nv_bfloat16 g_ol[(size_t)LEN * DIM];

// ---------------- helpers ----------------
static __device__ __forceinline__ unsigned cvta_smem(const void* p) {
    return (unsigned)__cvta_generic_to_shared(p);
}

static __device__ __forceinline__ unsigned pack2(float x0, float x1) {
    unsigned r;
    asm("cvt.rn.bf16x2.f32 %0, %1, %2;" : "=r"(r) : "f"(x1), "f"(x0));
    return r;
}
static __device__ __forceinline__ void split2(float x0, float x1,
                                              unsigned& hi, unsigned& lo) {
    unsigned h = pack2(x0, x1);
    float h0 = __uint_as_float(h << 16);
    float h1 = __uint_as_float(h & 0xffff0000u);
    lo = pack2(x0 - h0, x1 - h1);
    hi = h;
}

#define LDSM4(r0, r1, r2, r3, addr)                                         \
    asm volatile("ldmatrix.sync.aligned.m8n8.x4.shared.b16 {%0,%1,%2,%3}, [%4];" \
                 : "=r"(r0), "=r"(r1), "=r"(r2), "=r"(r3) : "r"(addr))

#define MMA16816(d, a, b0_, b1_)                                            \
    asm volatile("mma.sync.aligned.m16n8k16.row.col.f32.bf16.bf16.f32 "    \
                 "{%0,%1,%2,%3},{%4,%5,%6,%7},{%8,%9},{%0,%1,%2,%3};"      \
                 : "+f"(d[0]), "+f"(d[1]), "+f"(d[2]), "+f"(d[3])           \
                 : "r"(a[0]), "r"(a[1]), "r"(a[2]), "r"(a[3]),              \
                   "r"(b0_), "r"(b1_))

#define CP_ASYNC16(dst, src) \
    asm volatile("cp.async.cg.shared.global [%0], [%1], 16;" \
                 :: "r"(dst), "l"(src) : "memory")
#define CP_COMMIT() asm volatile("cp.async.commit_group;" ::: "memory")
#define CP_WAIT1()  asm volatile("cp.async.wait_group 1;" ::: "memory")
#define CP_WAIT0()  asm volatile("cp.async.wait_group 0;" ::: "memory")

// ---------------- bf16x3 tensor-core NT GEMM (pre-split operands) --------------
// C = alpha * (Ah+Al) @ (Bh+Bl)^T (+bias), dropping Al*Bl.
// CTA tile 128x128, BK=64, 512 threads (16 warps, warp tile 32x32),
// 3-stage cp.async pipeline, SW128-style swizzle, ldmatrix + mma.sync.
// Requires M,N mult of 128; K mult of 64; lda,ldb mult of 8.
// smem: 3 stages x (Ah,Al,Bh,Bl each 128x64x2B = 16KB) = 192KB
#define GSMEM (3 * 65536)

// loads one 128x64 bf16 tile into swizzled smem (1024 x 16B chunks, 512 threads)
static __device__ __forceinline__ void load_tile(
    unsigned sbase, const __nv_bfloat16* __restrict__ A,
    int ld, int kbase, int tid)
{
#pragma unroll
    for (int i = 0; i < 2; ++i) {
        const int idx = tid + i * 512;
        const int row = idx >> 3;
        const int ch  = idx & 7;
        const unsigned dst = sbase + row * 128 + ((ch * 16) ^ ((row & 7) * 16));
        const __nv_bfloat16* src = A + (long long)row * ld + kbase + ch * 8;
        CP_ASYNC16(dst, src);
    }
}

__global__ __launch_bounds__(512, 1)
void gemm_nt_bf3(const __nv_bfloat16* __restrict__ Ah,
                 const __nv_bfloat16* __restrict__ Al,
                 const __nv_bfloat16* __restrict__ Bh,
                 const __nv_bfloat16* __restrict__ Bl,
                 float* __restrict__ Cf,
                 __nv_bfloat16* __restrict__ Ch,
                 __nv_bfloat16* __restrict__ Cl,
                 int K, int lda, int ldb, int ldc,
                 long long sA, long long sB, long long sC,
                 float alpha, const float* __restrict__ bias)
{
    extern __shared__ char smem[];
    const unsigned smem_b = cvta_smem(smem);

    const int tid  = threadIdx.x;
    const int wid  = tid >> 5;
    const int lane = tid & 31;
    const int wm = (wid & 3) * 32;     // warp row offset (0..96)
    const int wn = (wid >> 2) * 32;    // warp col offset (0..96)
    const int m0 = blockIdx.y * 128;
    const int n0 = blockIdx.x * 128;

    const long long zoff = blockIdx.z;
    Ah += zoff * sA; Al += zoff * sA;
    Bh += zoff * sB; Bl += zoff * sB;
    if (Cf) Cf += zoff * sC;
    if (Ch) { Ch += zoff * sC; Cl += zoff * sC; }

    const __nv_bfloat16* pAh = Ah + (long long)m0 * lda;
    const __nv_bfloat16* pAl = Al + (long long)m0 * lda;
    const __nv_bfloat16* pBh = Bh + (long long)n0 * ldb;
    const __nv_bfloat16* pBl = Bl + (long long)n0 * ldb;

    // fragment address components (swizzle: chunk bits4-6 ^= (row&7)<<4)
    unsigned offA0[2], mskA[2];
    const unsigned cbA = ((lane >> 4) & 1) * 16;
#pragma unroll
    for (int mt = 0; mt < 2; ++mt) {
        const int r = wm + mt * 16 + (lane & 15);
        offA0[mt] = r * 128;
        mskA[mt]  = (r & 7) * 16;
    }
    unsigned offB0[2], mskB[2];
    const unsigned cbB = ((lane >> 3) & 1) * 16;
#pragma unroll
    for (int p = 0; p < 2; ++p) {
        const int r = wn + p * 16 + (lane & 7) + ((lane >> 4) & 1) * 8;
        offB0[p] = r * 128;
        mskB[p]  = (r & 7) * 16;
    }

    float acc[2][4][4];
#pragma unroll
    for (int i = 0; i < 2; ++i)
#pragma unroll
        for (int j = 0; j < 4; ++j)
#pragma unroll
            for (int v = 0; v < 4; ++v) acc[i][j][v] = 0.0f;

    const int nch = K >> 6;

    // prologue: stages 0 and 1
#pragma unroll
    for (int pc = 0; pc < 2; ++pc) {
        if (pc < nch) {
            const unsigned sb = smem_b + pc * 65536;
            const int kb = pc * 64;
            load_tile(sb,          pAh, lda, kb, tid);
            load_tile(sb + 16384,  pAl, lda, kb, tid);
            load_tile(sb + 32768,  pBh, ldb, kb, tid);
            load_tile(sb + 49152,  pBl, ldb, kb, tid);
            CP_COMMIT();
        }
    }

    for (int c = 0; c < nch; ++c) {
        if (c + 1 < nch) { CP_WAIT1(); } else { CP_WAIT0(); }
        __syncthreads();

        const unsigned sb = smem_b + (c % 3) * 65536;
#pragma unroll
        for (int ks = 0; ks < 4; ++ks) {
            const unsigned kb = ks * 32;
            unsigned ah[2][4], al[2][4], bh[2][4], bl[2][4];
#pragma unroll
            for (int mt = 0; mt < 2; ++mt) {
                const unsigned a0 = sb + offA0[mt] + ((cbA + kb) ^ mskA[mt]);
                LDSM4(ah[mt][0], ah[mt][1], ah[mt][2], ah[mt][3], a0);
                LDSM4(al[mt][0], al[mt][1], al[mt][2], al[mt][3], a0 + 16384);
            }
#pragma unroll
            for (int p = 0; p < 2; ++p) {
                const unsigned b0 = sb + 32768 + offB0[p] + ((cbB + kb) ^ mskB[p]);
                LDSM4(bh[p][0], bh[p][1], bh[p][2], bh[p][3], b0);
                LDSM4(bl[p][0], bl[p][1], bl[p][2], bl[p][3], b0 + 16384);
            }
#pragma unroll
            for (int mt = 0; mt < 2; ++mt) {
#pragma unroll
                for (int nt = 0; nt < 4; ++nt) {
                    const int p = nt >> 1, q = (nt & 1) * 2;
                    MMA16816(acc[mt][nt], ah[mt], bh[p][q], bh[p][q + 1]);
                    MMA16816(acc[mt][nt], ah[mt], bl[p][q], bl[p][q + 1]);
                    MMA16816(acc[mt][nt], al[mt], bh[p][q], bh[p][q + 1]);
                }
            }
        }
        __syncthreads();

        if (c + 2 < nch) {
            const unsigned sb2 = smem_b + ((c + 2) % 3) * 65536;
            const int kb = (c + 2) * 64;
            load_tile(sb2,          pAh, lda, kb, tid);
            load_tile(sb2 + 16384,  pAl, lda, kb, tid);
            load_tile(sb2 + 32768,  pBh, ldb, kb, tid);
            load_tile(sb2 + 49152,  pBl, ldb, kb, tid);
            CP_COMMIT();
        }
    }

    // epilogue
    const int g  = lane >> 2;
    const int tg = lane & 3;
#pragma unroll
    for (int mt = 0; mt < 2; ++mt) {
#pragma unroll
        for (int nt = 0; nt < 4; ++nt) {
            const int r = m0 + wm + mt * 16 + g;
            const int c = n0 + wn + nt * 8 + tg * 2;
            float bx = 0.0f, by = 0.0f;
            if (bias) { bx = bias[c]; by = bias[c + 1]; }
            float v00 = acc[mt][nt][0] * alpha + bx;
            float v01 = acc[mt][nt][1] * alpha + by;
            float v10 = acc[mt][nt][2] * alpha + bx;
            float v11 = acc[mt][nt][3] * alpha + by;
            if (Cf) {
                *reinterpret_cast<float2*>(&Cf[(long long)r * ldc + c]) =
                    make_float2(v00, v01);
                *reinterpret_cast<float2*>(&Cf[(long long)(r + 8) * ldc + c]) =
                    make_float2(v10, v11);
            }
            if (Ch) {
                unsigned h0, l0, h1, l1;
                split2(v00, v01, h0, l0);
                split2(v10, v11, h1, l1);
                *reinterpret_cast<unsigned*>(&Ch[(long long)r * ldc + c]) = h0;
                *reinterpret_cast<unsigned*>(&Cl[(long long)r * ldc + c]) = l0;
                *reinterpret_cast<unsigned*>(&Ch[(long long)(r + 8) * ldc + c]) = h1;
                *reinterpret_cast<unsigned*>(&Cl[(long long)(r + 8) * ldc + c]) = l1;
            }
        }
    }
}

// ---------------- pre-split x, w_qkv, w_proj into bf16 hi/lo ----------------
#define SEG_X  (LEN * DIM / 4)
#define SEG_WQ (3 * DIM * DIM / 4)
#define SEG_WP (DIM * DIM / 4)
__global__ void split_inputs(const float* __restrict__ x,
                             const float* __restrict__ wq,
                             const float* __restrict__ wp)
{
    const int i = blockIdx.x * blockDim.x + threadIdx.x;
    const float* src;
    __nv_bfloat16 *dh, *dl;
    int j;
    if (i < SEG_X)                  { src = x;  dh = g_xh;  dl = g_xl;  j = i; }
    else if (i < SEG_X + SEG_WQ)    { src = wq; dh = g_wqh; dl = g_wql; j = i - SEG_X; }
    else if (i < SEG_X + SEG_WQ + SEG_WP)
                                    { src = wp; dh = g_wph; dl = g_wpl; j = i - SEG_X - SEG_WQ; }
    else return;

    float4 v = reinterpret_cast<const float4*>(src)[j];
    unsigned h0, l0, h1, l1;
    split2(v.x, v.y, h0, l0);
    split2(v.z, v.w, h1, l1);
    reinterpret_cast<uint2*>(dh)[j] = make_uint2(h0, h1);
    reinterpret_cast<uint2*>(dl)[j] = make_uint2(l0, l1);
}

// ---------------- QK RMSNorm + RoPE + V transpose (split outputs) ----------------
__global__ void qknorm_rope(const float* __restrict__ pe,
                            const float* __restrict__ qs,
                            const float* __restrict__ ks)
{
    const int l = blockIdx.x;
    const int h = blockIdx.y;
    const int d = threadIdx.x;

    const float* base = g_qkv + (size_t)l * (3 * DIM) + h * HD;
    float q = base[d];
    float k = base[DIM + d];
    float v = base[2 * DIM + d];

    float sq = q * q, sk = k * k;
#pragma unroll
    for (int o = 16; o; o >>= 1) {
        sq += __shfl_xor_sync(0xffffffffu, sq, o);
        sk += __shfl_xor_sync(0xffffffffu, sk, o);
    }
    __shared__ float rq[4], rk[4];
    const int w = d >> 5;
    if ((d & 31) == 0) { rq[w] = sq; rk[w] = sk; }
    __syncthreads();
    sq = rq[0] + rq[1] + rq[2] + rq[3];
    sk = rk[0] + rk[1] + rk[2] + rk[3];

    const float rrq = rsqrtf(sq * (1.0f / HD) + 1e-6f);
    const float rrk = rsqrtf(sk * (1.0f / HD) + 1e-6f);
    float qn = q * rrq * qs[d];
    float kn = k * rrk * ks[d];

    const float qp = __shfl_xor_sync(0xffffffffu, qn, 1);
    const float kp = __shfl_xor_sync(0xffffffffu, kn, 1);
    const int j = d >> 1, a = d & 1;
    const float* p = pe + (size_t)l * (HD / 2) * 4 + j * 4 + a * 2;
    const float q0 = a ? qp : qn, q1 = a ? qn : qp;
    const float k0 = a ? kp : kn, k1 = a ? kn : kp;
    const float qr = p[0] * q0 + p[1] * q1;
    const float kr = p[0] * k0 + p[1] * k1;

    const size_t idx = ((size_t)h * LEN + l) * HD + d;
    __nv_bfloat16 qh = __float2bfloat16_rn(qr);
    __nv_bfloat16 kh = __float2bfloat16_rn(kr);
    g_qh[idx] = qh;
    g_ql[idx] = __float2bfloat16_rn(qr - __bfloat162float(qh));
    g_kh[idx] = kh;
    g_kl[idx] = __float2bfloat16_rn(kr - __bfloat162float(kh));

    const size_t vidx = ((size_t)h * HD + d) * LEN + l;
    __nv_bfloat16 vh = __float2bfloat16_rn(v);
    g_vth[vidx] = vh;
    g_vtl[vidx] = __float2bfloat16_rn(v - __bfloat162float(vh));
}

// ---------------- row softmax: fp32 logits -> bf16 hi/lo probs ----------------
__global__ void softmax_rows()
{
    const size_t base = (size_t)blockIdx.x * LEN;
    const float* s = g_s + base;
    const int t = threadIdx.x;
    const int i0 = t * 8;

    float vals[8];
    *reinterpret_cast<float4*>(vals)     = *reinterpret_cast<const float4*>(&s[i0]);
    *reinterpret_cast<float4*>(vals + 4) = *reinterpret_cast<const float4*>(&s[i0 + 4]);

    float mx = -INFINITY;
#pragma unroll
    for (int i = 0; i < 8; ++i) mx = fmaxf(mx, vals[i]);
#pragma unroll
    for (int o = 16; o; o >>= 1)
        mx = fmaxf(mx, __shfl_xor_sync(0xffffffffu, mx, o));
    __shared__ float red[8];
    const int w = t >> 5;
    if ((t & 31) == 0) red[w] = mx;
    __syncthreads();
    mx = red[0];
#pragma unroll
    for (int i = 1; i < 8; ++i) mx = fmaxf(mx, red[i]);

    float sum = 0.0f;
#pragma unroll
    for (int i = 0; i < 8; ++i) {
        vals[i] = __expf(vals[i] - mx);
        sum += vals[i];
    }
#pragma unroll
    for (int o = 16; o; o >>= 1)
        sum += __shfl_xor_sync(0xffffffffu, sum, o);
    __syncthreads();
    if ((t & 31) == 0) red[w] = sum;
    __syncthreads();
    sum = red[0];
#pragma unroll
    for (int i = 1; i < 8; ++i) sum += red[i];

    const float inv = 1.0f / sum;
    unsigned hp[4], lp[4];
#pragma unroll
    for (int i = 0; i < 4; ++i) {
        float p0 = vals[2 * i] * inv;
        float p1 = vals[2 * i + 1] * inv;
        split2(p0, p1, hp[i], lp[i]);
    }
    *reinterpret_cast<uint4*>(
        reinterpret_cast<unsigned*>(g_ph) + (base + i0) / 2) =
        make_uint4(hp[0], hp[1], hp[2], hp[3]);
    *reinterpret_cast<uint4*>(
        reinterpret_cast<unsigned*>(g_pl) + (base + i0) / 2) =
        make_uint4(lp[0], lp[1], lp[2], lp[3]);
}

// ---------------- launch ----------------
extern "C" void kernel_launch(void* const* d_in, const int* in_sizes, int n_in,
                              void* d_out, int out_size)
{
    const float* x      = (const float*)d_in[0];  // [L, DIM]
    const float* pe     = (const float*)d_in[1];  // [L, D/2, 2, 2]
    const float* w_qkv  = (const float*)d_in[2];  // [3*DIM, DIM]
    const float* q_sc   = (const float*)d_in[3];  // [D]
    const float* k_sc   = (const float*)d_in[4];  // [D]
    const float* w_proj = (const float*)d_in[5];  // [DIM, DIM]
    const float* b_proj = (const float*)d_in[6];  // [DIM]
    float* out = (float*)d_out;

    float *p_qkv, *p_s;
    __nv_bfloat16 *p_xh, *p_xl, *p_wqh, *p_wql, *p_wph, *p_wpl;
    __nv_bfloat16 *p_qh, *p_ql, *p_kh, *p_kl, *p_vth, *p_vtl;
    __nv_bfloat16 *p_ph, *p_pl, *p_oh, *p_ol;
    cudaGetSymbolAddress((void**)&p_qkv, g_qkv);
    cudaGetSymbolAddress((void**)&p_s,   g_s);
    cudaGetSymbolAddress((void**)&p_xh,  g_xh);
    cudaGetSymbolAddress((void**)&p_xl,  g_xl);
    cudaGetSymbolAddress((void**)&p_wqh, g_wqh);
    cudaGetSymbolAddress((void**)&p_wql, g_wql);
    cudaGetSymbolAddress((void**)&p_wph, g_wph);
    cudaGetSymbolAddress((void**)&p_wpl, g_wpl);
    cudaGetSymbolAddress((void**)&p_qh,  g_qh);
    cudaGetSymbolAddress((void**)&p_ql,  g_ql);
    cudaGetSymbolAddress((void**)&p_kh,  g_kh);
    cudaGetSymbolAddress((void**)&p_kl,  g_kl);
    cudaGetSymbolAddress((void**)&p_vth, g_vth);
    cudaGetSymbolAddress((void**)&p_vtl, g_vtl);
    cudaGetSymbolAddress((void**)&p_ph,  g_ph);
    cudaGetSymbolAddress((void**)&p_pl,  g_pl);
    cudaGetSymbolAddress((void**)&p_oh,  g_oh);
    cudaGetSymbolAddress((void**)&p_ol,  g_ol);

    cudaFuncSetAttribute(gemm_nt_bf3,
                         cudaFuncAttributeMaxDynamicSharedMemorySize, GSMEM);

    // 0) pre-split x, w_qkv, w_proj
    {
        const int total = SEG_X + SEG_WQ + SEG_WP;
        split_inputs<<<(total + 255) / 256, 256>>>(x, w_qkv, w_proj);
    }

    // 1) QKV = x @ w_qkv^T : [2048, 6144] fp32
    gemm_nt_bf3<<<dim3(6144 / 128, 2048 / 128, 1), 512, GSMEM>>>(
        p_xh, p_xl, p_wqh, p_wql, p_qkv, nullptr, nullptr,
        2048, 2048, 2048, 6144, 0, 0, 0, 1.0f, nullptr);

    // 2) QK RMSNorm + RoPE + V transpose (bf16 hi/lo outputs)
    qknorm_rope<<<dim3(LEN, NH), HD>>>(pe, q_sc, k_sc);

    // 3) S = scale * Q K^T per head : [H, 2048, 2048] fp32
    gemm_nt_bf3<<<dim3(2048 / 128, 2048 / 128, NH), 512, GSMEM>>>(
        p_qh, p_ql, p_kh, p_kl, p_s, nullptr, nullptr,
        HD, HD, HD, 2048,
        (long long)LEN * HD, (long long)LEN * HD, (long long)LEN * LEN,
        SCALE, nullptr);

    // 4) row softmax -> bf16 hi/lo probs
    softmax_rows<<<NH * LEN, 256>>>();

    // 5) O = P @ V per head -> bf16 hi/lo into [L, H*D] at column h*128
    gemm_nt_bf3<<<dim3(HD / 128, 2048 / 128, NH), 512, GSMEM>>>(
        p_ph, p_pl, p_vth, p_vtl, nullptr, p_oh, p_ol,
        2048, 2048, 2048, 2048,
        (long long)LEN * LEN, (long long)HD * LEN, (long long)HD,
        1.0f, nullptr);

    // 6) out = O @ w_proj^T + b_proj : [2048, 2048] fp32
    gemm_nt_bf3<<<dim3(2048 / 128, 2048 / 128, 1), 512, GSMEM>>>(
        p_oh, p_ol, p_wph, p_wpl, out, nullptr, nullptr,
        2048, 2048, 2048, 2048, 0, 0, 0, 1.0f, b_proj);
}

// round 6
// speedup vs baseline: 1.1075x; 1.1075x over previous
#include <cuda_runtime.h>
#include <cuda_bf16.h>
#include <math.h>
#include <stdint.h>

#define LEN 2048
#define DIM 2048
#define NH 16
#define HD 128
#define SCALE 0.08838834764831845f  /* 1/sqrt(128) */

// ---------------- scratch (allocation-free: __device__ globals) ----------------
__device__ float g_qkv[(size_t)LEN * 3 * DIM];               // [L, 3*DIM] fp32
__device__ float g_s[(size_t)NH * LEN * LEN];                // [H, L, L] logits fp32

__device__ __nv_bfloat16 g_xh[(size_t)LEN * DIM];
__device__ __nv_bfloat16 g_xl[(size_t)LEN * DIM];
__device__ __nv_bfloat16 g_wqh[(size_t)3 * DIM * DIM];
__device__ __nv_bfloat16 g_wql[(size_t)3 * DIM * DIM];
__device__ __nv_bfloat16 g_wph[(size_t)DIM * DIM];
__device__ __nv_bfloat16 g_wpl[(size_t)DIM * DIM];
__device__ __nv_bfloat16 g_qh[(size_t)NH * LEN * HD];
__device__ __nv_bfloat16 g_ql[(size_t)NH * LEN * HD];
__device__ __nv_bfloat16 g_kh[(size_t)NH * LEN * HD];
__device__ __nv_bfloat16 g_kl[(size_t)NH * LEN * HD];
__device__ __nv_bfloat16 g_vth[(size_t)NH * HD * LEN];
__device__ __nv_bfloat16 g_vtl[(size_t)NH * HD * LEN];
__device__ __nv_bfloat16 g_ph[(size_t)NH * LEN * LEN];
__device__ __nv_bfloat16 g_pl[(size_t)NH * LEN * LEN];
__device__ __nv_bfloat16 g_oh[(size_t)LEN * DIM];
__device__ __nv_bfloat16 g_ol[(size_t)LEN * DIM];

// ---------------- helpers ----------------
static __device__ __forceinline__ unsigned cvta_smem(const void* p) {
    return (unsigned)__cvta_generic_to_shared(p);
}
static __device__ __forceinline__ unsigned pack2(float x0, float x1) {
    unsigned r;
    asm("cvt.rn.bf16x2.f32 %0, %1, %2;" : "=r"(r) : "f"(x1), "f"(x0));
    return r;
}
static __device__ __forceinline__ void split2(float x0, float x1,
                                              unsigned& hi, unsigned& lo) {
    unsigned h = pack2(x0, x1);
    float h0 = __uint_as_float(h << 16);
    float h1 = __uint_as_float(h & 0xffff0000u);
    lo = pack2(x0 - h0, x1 - h1);
    hi = h;
}

#define LDSM4(r0, r1, r2, r3, addr)                                         \
    asm volatile("ldmatrix.sync.aligned.m8n8.x4.shared.b16 {%0,%1,%2,%3}, [%4];" \
                 : "=r"(r0), "=r"(r1), "=r"(r2), "=r"(r3) : "r"(addr))

#define MMA16816(d, a, b0_, b1_)                                            \
    asm volatile("mma.sync.aligned.m16n8k16.row.col.f32.bf16.bf16.f32 "    \
                 "{%0,%1,%2,%3},{%4,%5,%6,%7},{%8,%9},{%0,%1,%2,%3};"      \
                 : "+f"(d[0]), "+f"(d[1]), "+f"(d[2]), "+f"(d[3])           \
                 : "r"(a[0]), "r"(a[1]), "r"(a[2]), "r"(a[3]),              \
                   "r"(b0_), "r"(b1_))

#define CP_ASYNC16(dst, src) \
    asm volatile("cp.async.cg.shared.global [%0], [%1], 16;" \
                 :: "r"(dst), "l"(src) : "memory")
#define CP_COMMIT() asm volatile("cp.async.commit_group;" ::: "memory")
#define CP_WAIT1()  asm volatile("cp.async.wait_group 1;" ::: "memory")
#define CP_WAIT0()  asm volatile("cp.async.wait_group 0;" ::: "memory")

// loads one ROWSx64 bf16 tile into swizzled smem, 256 threads
template<int ROWS>
static __device__ __forceinline__ void load_tile(
    unsigned sbase, const __nv_bfloat16* __restrict__ A,
    int ld, int kbase, int tid)
{
#pragma unroll
    for (int i = 0; i < ROWS / 32; ++i) {
        const int idx = tid + i * 256;
        const int row = idx >> 3;
        const int ch  = idx & 7;
        const unsigned dst = sbase + row * 128 + ((ch * 16) ^ ((row & 7) * 16));
        const __nv_bfloat16* src = A + (long long)row * ld + kbase + ch * 8;
        CP_ASYNC16(dst, src);
    }
}

// ---------------- bf16x3 tensor-core NT GEMM (pre-split operands) --------------
// C = alpha * (Ah+Al) @ (Bh+Bl)^T (+bias), dropping Al*Bl.
// CTA tile 128 x BN, 256 threads (8 warps, 2(m) x 4(n), warp tile 64 x WN),
// BK=64, 2-stage cp.async pipeline, swizzled smem, ldmatrix + mma.sync.
// Requires M mult of 128, N mult of BN, K mult of 64, lda/ldb mult of 8.
template<int BN, int WN>
__global__ __launch_bounds__(256, 1)
void gemm_nt_bf3(const __nv_bfloat16* __restrict__ Ah,
                 const __nv_bfloat16* __restrict__ Al,
                 const __nv_bfloat16* __restrict__ Bh,
                 const __nv_bfloat16* __restrict__ Bl,
                 float* __restrict__ Cf,
                 __nv_bfloat16* __restrict__ Ch,
                 __nv_bfloat16* __restrict__ Cl,
                 int K, int lda, int ldb, int ldc,
                 long long sA, long long sB, long long sC,
                 float alpha, const float* __restrict__ bias)
{
    constexpr int NT16  = WN / 16;          // n16 tiles per warp
    constexpr int AT    = 128 * 64 * 2;     // 16384 bytes per A tile
    constexpr int BT    = BN * 64 * 2;      // bytes per B tile
    constexpr int STAGE = 2 * AT + 2 * BT;  // Ah,Al,Bh,Bl

    extern __shared__ char smem[];
    const unsigned smem_b = cvta_smem(smem);

    const int tid  = threadIdx.x;
    const int wid  = tid >> 5;
    const int lane = tid & 31;
    const int wm = (wid >> 2) * 64;        // 0 or 64
    const int wn = (wid & 3) * WN;         // 0..3*WN
    const int m0 = blockIdx.y * 128;
    const int n0 = blockIdx.x * BN;

    const long long zoff = blockIdx.z;
    Ah += zoff * sA; Al += zoff * sA;
    Bh += zoff * sB; Bl += zoff * sB;
    if (Cf) Cf += zoff * sC;
    if (Ch) { Ch += zoff * sC; Cl += zoff * sC; }

    const __nv_bfloat16* pAh = Ah + (long long)m0 * lda;
    const __nv_bfloat16* pAl = Al + (long long)m0 * lda;
    const __nv_bfloat16* pBh = Bh + (long long)n0 * ldb;
    const __nv_bfloat16* pBl = Bl + (long long)n0 * ldb;

    // fragment address components (swizzle: chunk bits4-6 ^= (row&7)<<4)
    unsigned offA0[4], mskA[4];
    const unsigned cbA = ((lane >> 4) & 1) * 16;
#pragma unroll
    for (int mt = 0; mt < 4; ++mt) {
        const int r = wm + mt * 16 + (lane & 15);
        offA0[mt] = r * 128;
        mskA[mt]  = (r & 7) * 16;
    }
    unsigned offB0[NT16], mskB[NT16];
    const unsigned cbB = ((lane >> 3) & 1) * 16;
#pragma unroll
    for (int p = 0; p < NT16; ++p) {
        const int r = wn + p * 16 + (lane & 7) + ((lane >> 4) & 1) * 8;
        offB0[p] = r * 128;
        mskB[p]  = (r & 7) * 16;
    }

    float acc[4][2 * NT16][4];
#pragma unroll
    for (int i = 0; i < 4; ++i)
#pragma unroll
        for (int j = 0; j < 2 * NT16; ++j)
#pragma unroll
            for (int v = 0; v < 4; ++v) acc[i][j][v] = 0.0f;

    const int nch = K >> 6;

    // prologue: stage 0
    load_tile<128>(smem_b,              pAh, lda, 0, tid);
    load_tile<128>(smem_b + AT,         pAl, lda, 0, tid);
    load_tile<BN> (smem_b + 2 * AT,     pBh, ldb, 0, tid);
    load_tile<BN> (smem_b + 2 * AT + BT, pBl, ldb, 0, tid);
    CP_COMMIT();

    for (int c = 0; c < nch; ++c) {
        if (c + 1 < nch) {
            const unsigned sb = smem_b + ((c + 1) & 1) * STAGE;
            const int kb = (c + 1) * 64;
            load_tile<128>(sb,              pAh, lda, kb, tid);
            load_tile<128>(sb + AT,         pAl, lda, kb, tid);
            load_tile<BN> (sb + 2 * AT,     pBh, ldb, kb, tid);
            load_tile<BN> (sb + 2 * AT + BT, pBl, ldb, kb, tid);
            CP_COMMIT();
            CP_WAIT1();
        } else {
            CP_WAIT0();
        }
        __syncthreads();

        const unsigned sb = smem_b + (c & 1) * STAGE;
#pragma unroll
        for (int ks = 0; ks < 4; ++ks) {
            const unsigned kb = ks * 32;
            unsigned ah[4][4], al[4][4];
#pragma unroll
            for (int mt = 0; mt < 4; ++mt) {
                const unsigned a0 = sb + offA0[mt] + ((cbA + kb) ^ mskA[mt]);
                LDSM4(ah[mt][0], ah[mt][1], ah[mt][2], ah[mt][3], a0);
                LDSM4(al[mt][0], al[mt][1], al[mt][2], al[mt][3], a0 + AT);
            }
#pragma unroll
            for (int p = 0; p < NT16; ++p) {
                const unsigned b0 = sb + 2 * AT + offB0[p] + ((cbB + kb) ^ mskB[p]);
                {
                    unsigned bh[4];
                    LDSM4(bh[0], bh[1], bh[2], bh[3], b0);
#pragma unroll
                    for (int mt = 0; mt < 4; ++mt) {
                        MMA16816(acc[mt][2 * p],     ah[mt], bh[0], bh[1]);
                        MMA16816(acc[mt][2 * p + 1], ah[mt], bh[2], bh[3]);
                        MMA16816(acc[mt][2 * p],     al[mt], bh[0], bh[1]);
                        MMA16816(acc[mt][2 * p + 1], al[mt], bh[2], bh[3]);
                    }
                }
                {
                    unsigned bl[4];
                    LDSM4(bl[0], bl[1], bl[2], bl[3], b0 + BT);
#pragma unroll
                    for (int mt = 0; mt < 4; ++mt) {
                        MMA16816(acc[mt][2 * p],     ah[mt], bl[0], bl[1]);
                        MMA16816(acc[mt][2 * p + 1], ah[mt], bl[2], bl[3]);
                    }
                }
            }
        }
        __syncthreads();
    }

    // epilogue
    const int g  = lane >> 2;
    const int tg = lane & 3;
#pragma unroll
    for (int mt = 0; mt < 4; ++mt) {
#pragma unroll
        for (int nt = 0; nt < 2 * NT16; ++nt) {
            const int r = m0 + wm + mt * 16 + g;
            const int c = n0 + wn + nt * 8 + tg * 2;
            float bx = 0.0f, by = 0.0f;
            if (bias) { bx = bias[c]; by = bias[c + 1]; }
            float v00 = acc[mt][nt][0] * alpha + bx;
            float v01 = acc[mt][nt][1] * alpha + by;
            float v10 = acc[mt][nt][2] * alpha + bx;
            float v11 = acc[mt][nt][3] * alpha + by;
            if (Cf) {
                *reinterpret_cast<float2*>(&Cf[(long long)r * ldc + c]) =
                    make_float2(v00, v01);
                *reinterpret_cast<float2*>(&Cf[(long long)(r + 8) * ldc + c]) =
                    make_float2(v10, v11);
            }
            if (Ch) {
                unsigned h0, l0, h1, l1;
                split2(v00, v01, h0, l0);
                split2(v10, v11, h1, l1);
                *reinterpret_cast<unsigned*>(&Ch[(long long)r * ldc + c]) = h0;
                *reinterpret_cast<unsigned*>(&Cl[(long long)r * ldc + c]) = l0;
                *reinterpret_cast<unsigned*>(&Ch[(long long)(r + 8) * ldc + c]) = h1;
                *reinterpret_cast<unsigned*>(&Cl[(long long)(r + 8) * ldc + c]) = l1;
            }
        }
    }
}

#define GSMEM_256 (2 * (2 * 16384 + 2 * 256 * 64 * 2))   /* 196608 */
#define GSMEM_128 (2 * (2 * 16384 + 2 * 128 * 64 * 2))   /* 131072 */

// ---------------- pre-split x, w_qkv, w_proj into bf16 hi/lo ----------------
#define SEG_X  (LEN * DIM / 4)
#define SEG_WQ (3 * DIM * DIM / 4)
#define SEG_WP (DIM * DIM / 4)
__global__ void split_inputs(const float* __restrict__ x,
                             const float* __restrict__ wq,
                             const float* __restrict__ wp)
{
    const int i = blockIdx.x * blockDim.x + threadIdx.x;
    const float* src;
    __nv_bfloat16 *dh, *dl;
    int j;
    if (i < SEG_X)                  { src = x;  dh = g_xh;  dl = g_xl;  j = i; }
    else if (i < SEG_X + SEG_WQ)    { src = wq; dh = g_wqh; dl = g_wql; j = i - SEG_X; }
    else if (i < SEG_X + SEG_WQ + SEG_WP)
                                    { src = wp; dh = g_wph; dl = g_wpl; j = i - SEG_X - SEG_WQ; }
    else return;

    float4 v = reinterpret_cast<const float4*>(src)[j];
    unsigned h0, l0, h1, l1;
    split2(v.x, v.y, h0, l0);
    split2(v.z, v.w, h1, l1);
    reinterpret_cast<uint2*>(dh)[j] = make_uint2(h0, h1);
    reinterpret_cast<uint2*>(dl)[j] = make_uint2(l0, l1);
}

// ---------------- QK RMSNorm + RoPE + V transpose (split outputs) ----------------
__global__ void qknorm_rope(const float* __restrict__ pe,
                            const float* __restrict__ qs,
                            const float* __restrict__ ks)
{
    const int l = blockIdx.x;
    const int h = blockIdx.y;
    const int d = threadIdx.x;

    const float* base = g_qkv + (size_t)l * (3 * DIM) + h * HD;
    float q = base[d];
    float k = base[DIM + d];
    float v = base[2 * DIM + d];

    float sq = q * q, sk = k * k;
#pragma unroll
    for (int o = 16; o; o >>= 1) {
        sq += __shfl_xor_sync(0xffffffffu, sq, o);
        sk += __shfl_xor_sync(0xffffffffu, sk, o);
    }
    __shared__ float rq[4], rk[4];
    const int w = d >> 5;
    if ((d & 31) == 0) { rq[w] = sq; rk[w] = sk; }
    __syncthreads();
    sq = rq[0] + rq[1] + rq[2] + rq[3];
    sk = rk[0] + rk[1] + rk[2] + rk[3];

    const float rrq = rsqrtf(sq * (1.0f / HD) + 1e-6f);
    const float rrk = rsqrtf(sk * (1.0f / HD) + 1e-6f);
    float qn = q * rrq * qs[d];
    float kn = k * rrk * ks[d];

    const float qp = __shfl_xor_sync(0xffffffffu, qn, 1);
    const float kp = __shfl_xor_sync(0xffffffffu, kn, 1);
    const int j = d >> 1, a = d & 1;
    const float* p = pe + (size_t)l * (HD / 2) * 4 + j * 4 + a * 2;
    const float q0 = a ? qp : qn, q1 = a ? qn : qp;
    const float k0 = a ? kp : kn, k1 = a ? kn : kp;
    const float qr = p[0] * q0 + p[1] * q1;
    const float kr = p[0] * k0 + p[1] * k1;

    const size_t idx = ((size_t)h * LEN + l) * HD + d;
    __nv_bfloat16 qh = __float2bfloat16_rn(qr);
    __nv_bfloat16 kh = __float2bfloat16_rn(kr);
    g_qh[idx] = qh;
    g_ql[idx] = __float2bfloat16_rn(qr - __bfloat162float(qh));
    g_kh[idx] = kh;
    g_kl[idx] = __float2bfloat16_rn(kr - __bfloat162float(kh));

    const size_t vidx = ((size_t)h * HD + d) * LEN + l;
    __nv_bfloat16 vh = __float2bfloat16_rn(v);
    g_vth[vidx] = vh;
    g_vtl[vidx] = __float2bfloat16_rn(v - __bfloat162float(vh));
}

// ---------------- row softmax: fp32 logits -> bf16 hi/lo probs ----------------
__global__ void softmax_rows()
{
    const size_t base = (size_t)blockIdx.x * LEN;
    const float* s = g_s + base;
    const int t = threadIdx.x;
    const int i0 = t * 8;

    float vals[8];
    *reinterpret_cast<float4*>(vals)     = *reinterpret_cast<const float4*>(&s[i0]);
    *reinterpret_cast<float4*>(vals + 4) = *reinterpret_cast<const float4*>(&s[i0 + 4]);

    float mx = -INFINITY;
#pragma unroll
    for (int i = 0; i < 8; ++i) mx = fmaxf(mx, vals[i]);
#pragma unroll
    for (int o = 16; o; o >>= 1)
        mx = fmaxf(mx, __shfl_xor_sync(0xffffffffu, mx, o));
    __shared__ float red[8];
    const int w = t >> 5;
    if ((t & 31) == 0) red[w] = mx;
    __syncthreads();
    mx = red[0];
#pragma unroll
    for (int i = 1; i < 8; ++i) mx = fmaxf(mx, red[i]);

    float sum = 0.0f;
#pragma unroll
    for (int i = 0; i < 8; ++i) {
        vals[i] = __expf(vals[i] - mx);
        sum += vals[i];
    }
#pragma unroll
    for (int o = 16; o; o >>= 1)
        sum += __shfl_xor_sync(0xffffffffu, sum, o);
    __syncthreads();
    if ((t & 31) == 0) red[w] = sum;
    __syncthreads();
    sum = red[0];
#pragma unroll
    for (int i = 1; i < 8; ++i) sum += red[i];

    const float inv = 1.0f / sum;
    unsigned hp[4], lp[4];
#pragma unroll
    for (int i = 0; i < 4; ++i) {
        float p0 = vals[2 * i] * inv;
        float p1 = vals[2 * i + 1] * inv;
        split2(p0, p1, hp[i], lp[i]);
    }
    *reinterpret_cast<uint4*>(
        reinterpret_cast<unsigned*>(g_ph) + (base + i0) / 2) =
        make_uint4(hp[0], hp[1], hp[2], hp[3]);
    *reinterpret_cast<uint4*>(
        reinterpret_cast<unsigned*>(g_pl) + (base + i0) / 2) =
        make_uint4(lp[0], lp[1], lp[2], lp[3]);
}

// ---------------- launch ----------------
extern "C" void kernel_launch(void* const* d_in, const int* in_sizes, int n_in,
                              void* d_out, int out_size)
{
    const float* x      = (const float*)d_in[0];
    const float* pe     = (const float*)d_in[1];
    const float* w_qkv  = (const float*)d_in[2];
    const float* q_sc   = (const float*)d_in[3];
    const float* k_sc   = (const float*)d_in[4];
    const float* w_proj = (const float*)d_in[5];
    const float* b_proj = (const float*)d_in[6];
    float* out = (float*)d_out;

    float *p_qkv, *p_s;
    __nv_bfloat16 *p_xh, *p_xl, *p_wqh, *p_wql, *p_wph, *p_wpl;
    __nv_bfloat16 *p_qh, *p_ql, *p_kh, *p_kl, *p_vth, *p_vtl;
    __nv_bfloat16 *p_ph, *p_pl, *p_oh, *p_ol;
    cudaGetSymbolAddress((void**)&p_qkv, g_qkv);
    cudaGetSymbolAddress((void**)&p_s,   g_s);
    cudaGetSymbolAddress((void**)&p_xh,  g_xh);
    cudaGetSymbolAddress((void**)&p_xl,  g_xl);
    cudaGetSymbolAddress((void**)&p_wqh, g_wqh);
    cudaGetSymbolAddress((void**)&p_wql, g_wql);
    cudaGetSymbolAddress((void**)&p_wph, g_wph);
    cudaGetSymbolAddress((void**)&p_wpl, g_wpl);
    cudaGetSymbolAddress((void**)&p_qh,  g_qh);
    cudaGetSymbolAddress((void**)&p_ql,  g_ql);
    cudaGetSymbolAddress((void**)&p_kh,  g_kh);
    cudaGetSymbolAddress((void**)&p_kl,  g_kl);
    cudaGetSymbolAddress((void**)&p_vth, g_vth);
    cudaGetSymbolAddress((void**)&p_vtl, g_vtl);
    cudaGetSymbolAddress((void**)&p_ph,  g_ph);
    cudaGetSymbolAddress((void**)&p_pl,  g_pl);
    cudaGetSymbolAddress((void**)&p_oh,  g_oh);
    cudaGetSymbolAddress((void**)&p_ol,  g_ol);

    cudaFuncSetAttribute(gemm_nt_bf3<256, 64>,
                         cudaFuncAttributeMaxDynamicSharedMemorySize, GSMEM_256);
    cudaFuncSetAttribute(gemm_nt_bf3<128, 32>,
                         cudaFuncAttributeMaxDynamicSharedMemorySize, GSMEM_128);

    // 0) pre-split x, w_qkv, w_proj
    {
        const int total = SEG_X + SEG_WQ + SEG_WP;
        split_inputs<<<(total + 255) / 256, 256>>>(x, w_qkv, w_proj);
    }

    // 1) QKV = x @ w_qkv^T : [2048, 6144] fp32
    gemm_nt_bf3<256, 64><<<dim3(6144 / 256, 2048 / 128, 1), 256, GSMEM_256>>>(
        p_xh, p_xl, p_wqh, p_wql, p_qkv, nullptr, nullptr,
        2048, 2048, 2048, 6144, 0, 0, 0, 1.0f, nullptr);

    // 2) QK RMSNorm + RoPE + V transpose (bf16 hi/lo outputs)
    qknorm_rope<<<dim3(LEN, NH), HD>>>(pe, q_sc, k_sc);

    // 3) S = scale * Q K^T per head : [H, 2048, 2048] fp32
    gemm_nt_bf3<256, 64><<<dim3(2048 / 256, 2048 / 128, NH), 256, GSMEM_256>>>(
        p_qh, p_ql, p_kh, p_kl, p_s, nullptr, nullptr,
        HD, HD, HD, 2048,
        (long long)LEN * HD, (long long)LEN * HD, (long long)LEN * LEN,
        SCALE, nullptr);

    // 4) row softmax -> bf16 hi/lo probs
    softmax_rows<<<NH * LEN, 256>>>();

    // 5) O = P @ V per head -> bf16 hi/lo into [L, H*D] at column h*128
    gemm_nt_bf3<128, 32><<<dim3(HD / 128, 2048 / 128, NH), 256, GSMEM_128>>>(
        p_ph, p_pl, p_vth, p_vtl, nullptr, p_oh, p_ol,
        2048, 2048, 2048, 2048,
        (long long)LEN * LEN, (long long)HD * LEN, (long long)HD,
        1.0f, nullptr);

    // 6) out = O @ w_proj^T + b_proj : [2048, 2048] fp32
    gemm_nt_bf3<256, 64><<<dim3(2048 / 256, 2048 / 128, 1), 256, GSMEM_256>>>(
        p_oh, p_ol, p_wph, p_wpl, out, nullptr, nullptr,
        2048, 2048, 2048, 2048, 0, 0, 0, 1.0f, b_proj);
}

// round 7
// speedup vs baseline: 1.5310x; 1.3824x over previous
#include <cuda_runtime.h>
#include <cuda_fp16.h>
#include <math.h>
#include <stdint.h>

#define LEN 2048
#define DIM 2048
#define NH 16
#define HD 128
#define SCALE 0.08838834764831845f  /* 1/sqrt(128) */

// ---------------- scratch (allocation-free: __device__ globals) ----------------
__device__ float g_qkv[(size_t)LEN * 3 * DIM];               // [L, 3*DIM] fp32
__device__ float g_s[(size_t)NH * LEN * LEN];                // [H, L, L] logits fp32

__device__ __half g_xh[(size_t)LEN * DIM];                   // x hi/lo (A of QKV)
__device__ __half g_xl[(size_t)LEN * DIM];
__device__ __half g_wqh[(size_t)3 * DIM * DIM];              // w_qkv (B, hi only)
__device__ __half g_wph[(size_t)DIM * DIM];                  // w_proj (B, hi only)
__device__ __half g_qh[(size_t)NH * LEN * HD];               // q hi/lo (A of S)
__device__ __half g_ql[(size_t)NH * LEN * HD];
__device__ __half g_kh[(size_t)NH * LEN * HD];               // k (B, hi only)
__device__ __half g_vth[(size_t)NH * HD * LEN];              // v^T (B, hi only)
__device__ __half g_ph[(size_t)NH * LEN * LEN];              // probs hi/lo (A of PV)
__device__ __half g_pl[(size_t)NH * LEN * LEN];
__device__ __half g_oh[(size_t)LEN * DIM];                   // O hi/lo (A of proj)
__device__ __half g_ol[(size_t)LEN * DIM];

// ---------------- helpers ----------------
static __device__ __forceinline__ unsigned cvta_smem(const void* p) {
    return (unsigned)__cvta_generic_to_shared(p);
}
// pack two fp32 into f16x2
static __device__ __forceinline__ unsigned pack2h(float x0, float x1) {
    __half2 h = __floats2half2_rn(x0, x1);
    return *reinterpret_cast<unsigned*>(&h);
}
// split two fp32 into f16x2 hi and lo (x ~= hi + lo)
static __device__ __forceinline__ void split2h(float x0, float x1,
                                               unsigned& hi, unsigned& lo) {
    __half2 h = __floats2half2_rn(x0, x1);
    float2 f = __half22float2(h);
    __half2 l = __floats2half2_rn(x0 - f.x, x1 - f.y);
    hi = *reinterpret_cast<unsigned*>(&h);
    lo = *reinterpret_cast<unsigned*>(&l);
}

#define LDSM4(r0, r1, r2, r3, addr)                                         \
    asm volatile("ldmatrix.sync.aligned.m8n8.x4.shared.b16 {%0,%1,%2,%3}, [%4];" \
                 : "=r"(r0), "=r"(r1), "=r"(r2), "=r"(r3) : "r"(addr))

#define MMA16816(d, a, b0_, b1_)                                            \
    asm volatile("mma.sync.aligned.m16n8k16.row.col.f32.f16.f16.f32 "      \
                 "{%0,%1,%2,%3},{%4,%5,%6,%7},{%8,%9},{%0,%1,%2,%3};"      \
                 : "+f"(d[0]), "+f"(d[1]), "+f"(d[2]), "+f"(d[3])           \
                 : "r"(a[0]), "r"(a[1]), "r"(a[2]), "r"(a[3]),              \
                   "r"(b0_), "r"(b1_))

#define CP_ASYNC16(dst, src) \
    asm volatile("cp.async.cg.shared.global [%0], [%1], 16;" \
                 :: "r"(dst), "l"(src) : "memory")
#define CP_COMMIT() asm volatile("cp.async.commit_group;" ::: "memory")
#define CP_WAIT1()  asm volatile("cp.async.wait_group 1;" ::: "memory")
#define CP_WAIT0()  asm volatile("cp.async.wait_group 0;" ::: "memory")

// loads one ROWSx64 fp16 tile into swizzled smem, 256 threads
template<int ROWS>
static __device__ __forceinline__ void load_tile(
    unsigned sbase, const __half* __restrict__ A,
    int ld, int kbase, int tid)
{
#pragma unroll
    for (int i = 0; i < ROWS / 32; ++i) {
        const int idx = tid + i * 256;
        const int row = idx >> 3;
        const int ch  = idx & 7;
        const unsigned dst = sbase + row * 128 + ((ch * 16) ^ ((row & 7) * 16));
        const __half* src = A + (long long)row * ld + kbase + ch * 8;
        CP_ASYNC16(dst, src);
    }
}

// ---------------- fp16x2 tensor-core NT GEMM (A split, B single) ---------------
// C = alpha * (Ah+Al) @ Bh^T (+bias).
// CTA tile 128 x BN, 256 threads (8 warps, 2(m) x 4(n), warp tile 64 x WN),
// BK=64, 2-stage cp.async pipeline, swizzled smem, ldmatrix + mma.sync.
// Requires M mult of 128, N mult of BN, K mult of 64, lda/ldb mult of 8.
template<int BN, int WN>
__global__ __launch_bounds__(256, 1)
void gemm_nt_h2(const __half* __restrict__ Ah,
                const __half* __restrict__ Al,
                const __half* __restrict__ Bh,
                float* __restrict__ Cf,
                __half* __restrict__ Ch,
                __half* __restrict__ Cl,
                int K, int lda, int ldb, int ldc,
                long long sA, long long sB, long long sC,
                float alpha, const float* __restrict__ bias)
{
    constexpr int NT16  = WN / 16;          // n16 tiles per warp
    constexpr int AT    = 128 * 64 * 2;     // 16384 bytes per A tile
    constexpr int BT    = BN * 64 * 2;      // bytes per B tile
    constexpr int STAGE = 2 * AT + BT;      // Ah, Al, Bh

    extern __shared__ char smem[];
    const unsigned smem_b = cvta_smem(smem);

    const int tid  = threadIdx.x;
    const int wid  = tid >> 5;
    const int lane = tid & 31;
    const int wm = (wid >> 2) * 64;        // 0 or 64
    const int wn = (wid & 3) * WN;         // 0..3*WN
    const int m0 = blockIdx.y * 128;
    const int n0 = blockIdx.x * BN;

    const long long zoff = blockIdx.z;
    Ah += zoff * sA; Al += zoff * sA;
    Bh += zoff * sB;
    if (Cf) Cf += zoff * sC;
    if (Ch) { Ch += zoff * sC; Cl += zoff * sC; }

    const __half* pAh = Ah + (long long)m0 * lda;
    const __half* pAl = Al + (long long)m0 * lda;
    const __half* pBh = Bh + (long long)n0 * ldb;

    // fragment address components (swizzle: chunk bits4-6 ^= (row&7)<<4)
    unsigned offA0[4], mskA[4];
    const unsigned cbA = ((lane >> 4) & 1) * 16;
#pragma unroll
    for (int mt = 0; mt < 4; ++mt) {
        const int r = wm + mt * 16 + (lane & 15);
        offA0[mt] = r * 128;
        mskA[mt]  = (r & 7) * 16;
    }
    unsigned offB0[NT16], mskB[NT16];
    const unsigned cbB = ((lane >> 3) & 1) * 16;
#pragma unroll
    for (int p = 0; p < NT16; ++p) {
        const int r = wn + p * 16 + (lane & 7) + ((lane >> 4) & 1) * 8;
        offB0[p] = r * 128;
        mskB[p]  = (r & 7) * 16;
    }

    float acc[4][2 * NT16][4];
#pragma unroll
    for (int i = 0; i < 4; ++i)
#pragma unroll
        for (int j = 0; j < 2 * NT16; ++j)
#pragma unroll
            for (int v = 0; v < 4; ++v) acc[i][j][v] = 0.0f;

    const int nch = K >> 6;

    // prologue: stage 0
    load_tile<128>(smem_b,          pAh, lda, 0, tid);
    load_tile<128>(smem_b + AT,     pAl, lda, 0, tid);
    load_tile<BN> (smem_b + 2 * AT, pBh, ldb, 0, tid);
    CP_COMMIT();

    for (int c = 0; c < nch; ++c) {
        if (c + 1 < nch) {
            const unsigned sb = smem_b + ((c + 1) & 1) * STAGE;
            const int kb = (c + 1) * 64;
            load_tile<128>(sb,          pAh, lda, kb, tid);
            load_tile<128>(sb + AT,     pAl, lda, kb, tid);
            load_tile<BN> (sb + 2 * AT, pBh, ldb, kb, tid);
            CP_COMMIT();
            CP_WAIT1();
        } else {
            CP_WAIT0();
        }
        __syncthreads();

        const unsigned sb = smem_b + (c & 1) * STAGE;
#pragma unroll
        for (int ks = 0; ks < 4; ++ks) {
            const unsigned kb = ks * 32;
            unsigned ah[4][4], al[4][4];
#pragma unroll
            for (int mt = 0; mt < 4; ++mt) {
                const unsigned a0 = sb + offA0[mt] + ((cbA + kb) ^ mskA[mt]);
                LDSM4(ah[mt][0], ah[mt][1], ah[mt][2], ah[mt][3], a0);
                LDSM4(al[mt][0], al[mt][1], al[mt][2], al[mt][3], a0 + AT);
            }
#pragma unroll
            for (int p = 0; p < NT16; ++p) {
                const unsigned b0 = sb + 2 * AT + offB0[p] + ((cbB + kb) ^ mskB[p]);
                unsigned bh[4];
                LDSM4(bh[0], bh[1], bh[2], bh[3], b0);
#pragma unroll
                for (int mt = 0; mt < 4; ++mt) {
                    MMA16816(acc[mt][2 * p],     ah[mt], bh[0], bh[1]);
                    MMA16816(acc[mt][2 * p + 1], ah[mt], bh[2], bh[3]);
                    MMA16816(acc[mt][2 * p],     al[mt], bh[0], bh[1]);
                    MMA16816(acc[mt][2 * p + 1], al[mt], bh[2], bh[3]);
                }
            }
        }
        __syncthreads();
    }

    // epilogue
    const int g  = lane >> 2;
    const int tg = lane & 3;
#pragma unroll
    for (int mt = 0; mt < 4; ++mt) {
#pragma unroll
        for (int nt = 0; nt < 2 * NT16; ++nt) {
            const int r = m0 + wm + mt * 16 + g;
            const int c = n0 + wn + nt * 8 + tg * 2;
            float bx = 0.0f, by = 0.0f;
            if (bias) { bx = bias[c]; by = bias[c + 1]; }
            float v00 = acc[mt][nt][0] * alpha + bx;
            float v01 = acc[mt][nt][1] * alpha + by;
            float v10 = acc[mt][nt][2] * alpha + bx;
            float v11 = acc[mt][nt][3] * alpha + by;
            if (Cf) {
                *reinterpret_cast<float2*>(&Cf[(long long)r * ldc + c]) =
                    make_float2(v00, v01);
                *reinterpret_cast<float2*>(&Cf[(long long)(r + 8) * ldc + c]) =
                    make_float2(v10, v11);
            }
            if (Ch) {
                unsigned h0, l0, h1, l1;
                split2h(v00, v01, h0, l0);
                split2h(v10, v11, h1, l1);
                *reinterpret_cast<unsigned*>(&Ch[(long long)r * ldc + c]) = h0;
                *reinterpret_cast<unsigned*>(&Cl[(long long)r * ldc + c]) = l0;
                *reinterpret_cast<unsigned*>(&Ch[(long long)(r + 8) * ldc + c]) = h1;
                *reinterpret_cast<unsigned*>(&Cl[(long long)(r + 8) * ldc + c]) = l1;
            }
        }
    }
}

#define GSMEM_256 (2 * (2 * 16384 + 256 * 64 * 2))   /* 131072 */
#define GSMEM_128 (2 * (2 * 16384 + 128 * 64 * 2))   /* 98304  */

// ---------------- pre-split x; round w_qkv / w_proj to fp16 ----------------
#define SEG_X  (LEN * DIM / 4)
#define SEG_WQ (3 * DIM * DIM / 4)
#define SEG_WP (DIM * DIM / 4)
__global__ void split_inputs(const float* __restrict__ x,
                             const float* __restrict__ wq,
                             const float* __restrict__ wp)
{
    const int i = blockIdx.x * blockDim.x + threadIdx.x;
    if (i < SEG_X) {
        float4 v = reinterpret_cast<const float4*>(x)[i];
        unsigned h0, l0, h1, l1;
        split2h(v.x, v.y, h0, l0);
        split2h(v.z, v.w, h1, l1);
        reinterpret_cast<uint2*>(g_xh)[i] = make_uint2(h0, h1);
        reinterpret_cast<uint2*>(g_xl)[i] = make_uint2(l0, l1);
    } else if (i < SEG_X + SEG_WQ) {
        const int j = i - SEG_X;
        float4 v = reinterpret_cast<const float4*>(wq)[j];
        reinterpret_cast<uint2*>(g_wqh)[j] =
            make_uint2(pack2h(v.x, v.y), pack2h(v.z, v.w));
    } else if (i < SEG_X + SEG_WQ + SEG_WP) {
        const int j = i - SEG_X - SEG_WQ;
        float4 v = reinterpret_cast<const float4*>(wp)[j];
        reinterpret_cast<uint2*>(g_wph)[j] =
            make_uint2(pack2h(v.x, v.y), pack2h(v.z, v.w));
    }
}

// ---------------- QK RMSNorm + RoPE + V transpose ----------------
__global__ void qknorm_rope(const float* __restrict__ pe,
                            const float* __restrict__ qs,
                            const float* __restrict__ ks)
{
    const int l = blockIdx.x;
    const int h = blockIdx.y;
    const int d = threadIdx.x;

    const float* base = g_qkv + (size_t)l * (3 * DIM) + h * HD;
    float q = base[d];
    float k = base[DIM + d];
    float v = base[2 * DIM + d];

    float sq = q * q, sk = k * k;
#pragma unroll
    for (int o = 16; o; o >>= 1) {
        sq += __shfl_xor_sync(0xffffffffu, sq, o);
        sk += __shfl_xor_sync(0xffffffffu, sk, o);
    }
    __shared__ float rq[4], rk[4];
    const int w = d >> 5;
    if ((d & 31) == 0) { rq[w] = sq; rk[w] = sk; }
    __syncthreads();
    sq = rq[0] + rq[1] + rq[2] + rq[3];
    sk = rk[0] + rk[1] + rk[2] + rk[3];

    const float rrq = rsqrtf(sq * (1.0f / HD) + 1e-6f);
    const float rrk = rsqrtf(sk * (1.0f / HD) + 1e-6f);
    float qn = q * rrq * qs[d];
    float kn = k * rrk * ks[d];

    const float qp = __shfl_xor_sync(0xffffffffu, qn, 1);
    const float kp = __shfl_xor_sync(0xffffffffu, kn, 1);
    const int j = d >> 1, a = d & 1;
    const float* p = pe + (size_t)l * (HD / 2) * 4 + j * 4 + a * 2;
    const float q0 = a ? qp : qn, q1 = a ? qn : qp;
    const float k0 = a ? kp : kn, k1 = a ? kn : kp;
    const float qr = p[0] * q0 + p[1] * q1;
    const float kr = p[0] * k0 + p[1] * k1;

    const size_t idx = ((size_t)h * LEN + l) * HD + d;
    __half qh = __float2half_rn(qr);
    g_qh[idx] = qh;
    g_ql[idx] = __float2half_rn(qr - __half2float(qh));
    g_kh[idx] = __float2half_rn(kr);
    g_vth[((size_t)h * HD + d) * LEN + l] = __float2half_rn(v);
}

// ---------------- row softmax: fp32 logits -> fp16 hi/lo probs ----------------
__global__ void softmax_rows()
{
    const size_t base = (size_t)blockIdx.x * LEN;
    const float* s = g_s + base;
    const int t = threadIdx.x;
    const int i0 = t * 8;

    float vals[8];
    *reinterpret_cast<float4*>(vals)     = *reinterpret_cast<const float4*>(&s[i0]);
    *reinterpret_cast<float4*>(vals + 4) = *reinterpret_cast<const float4*>(&s[i0 + 4]);

    float mx = -INFINITY;
#pragma unroll
    for (int i = 0; i < 8; ++i) mx = fmaxf(mx, vals[i]);
#pragma unroll
    for (int o = 16; o; o >>= 1)
        mx = fmaxf(mx, __shfl_xor_sync(0xffffffffu, mx, o));
    __shared__ float red[8];
    const int w = t >> 5;
    if ((t & 31) == 0) red[w] = mx;
    __syncthreads();
    mx = red[0];
#pragma unroll
    for (int i = 1; i < 8; ++i) mx = fmaxf(mx, red[i]);

    float sum = 0.0f;
#pragma unroll
    for (int i = 0; i < 8; ++i) {
        vals[i] = __expf(vals[i] - mx);
        sum += vals[i];
    }
#pragma unroll
    for (int o = 16; o; o >>= 1)
        sum += __shfl_xor_sync(0xffffffffu, sum, o);
    __syncthreads();
    if ((t & 31) == 0) red[w] = sum;
    __syncthreads();
    sum = red[0];
#pragma unroll
    for (int i = 1; i < 8; ++i) sum += red[i];

    const float inv = 1.0f / sum;
    unsigned hp[4], lp[4];
#pragma unroll
    for (int i = 0; i < 4; ++i) {
        float p0 = vals[2 * i] * inv;
        float p1 = vals[2 * i + 1] * inv;
        split2h(p0, p1, hp[i], lp[i]);
    }
    *reinterpret_cast<uint4*>(
        reinterpret_cast<unsigned*>(g_ph) + (base + i0) / 2) =
        make_uint4(hp[0], hp[1], hp[2], hp[3]);
    *reinterpret_cast<uint4*>(
        reinterpret_cast<unsigned*>(g_pl) + (base + i0) / 2) =
        make_uint4(lp[0], lp[1], lp[2], lp[3]);
}

// ---------------- launch ----------------
extern "C" void kernel_launch(void* const* d_in, const int* in_sizes, int n_in,
                              void* d_out, int out_size)
{
    const float* x      = (const float*)d_in[0];
    const float* pe     = (const float*)d_in[1];
    const float* w_qkv  = (const float*)d_in[2];
    const float* q_sc   = (const float*)d_in[3];
    const float* k_sc   = (const float*)d_in[4];
    const float* w_proj = (const float*)d_in[5];
    const float* b_proj = (const float*)d_in[6];
    float* out = (float*)d_out;

    float *p_qkv, *p_s;
    __half *p_xh, *p_xl, *p_wqh, *p_wph;
    __half *p_qh, *p_ql, *p_kh, *p_vth;
    __half *p_ph, *p_pl, *p_oh, *p_ol;
    cudaGetSymbolAddress((void**)&p_qkv, g_qkv);
    cudaGetSymbolAddress((void**)&p_s,   g_s);
    cudaGetSymbolAddress((void**)&p_xh,  g_xh);
    cudaGetSymbolAddress((void**)&p_xl,  g_xl);
    cudaGetSymbolAddress((void**)&p_wqh, g_wqh);
    cudaGetSymbolAddress((void**)&p_wph, g_wph);
    cudaGetSymbolAddress((void**)&p_qh,  g_qh);
    cudaGetSymbolAddress((void**)&p_ql,  g_ql);
    cudaGetSymbolAddress((void**)&p_kh,  g_kh);
    cudaGetSymbolAddress((void**)&p_vth, g_vth);
    cudaGetSymbolAddress((void**)&p_ph,  g_ph);
    cudaGetSymbolAddress((void**)&p_pl,  g_pl);
    cudaGetSymbolAddress((void**)&p_oh,  g_oh);
    cudaGetSymbolAddress((void**)&p_ol,  g_ol);

    cudaFuncSetAttribute(gemm_nt_h2<256, 64>,
                         cudaFuncAttributeMaxDynamicSharedMemorySize, GSMEM_256);
    cudaFuncSetAttribute(gemm_nt_h2<128, 32>,
                         cudaFuncAttributeMaxDynamicSharedMemorySize, GSMEM_128);

    // 0) pre-split x; round weights
    {
        const int total = SEG_X + SEG_WQ + SEG_WP;
        split_inputs<<<(total + 255) / 256, 256>>>(x, w_qkv, w_proj);
    }

    // 1) QKV = x @ w_qkv^T : [2048, 6144] fp32
    gemm_nt_h2<256, 64><<<dim3(6144 / 256, 2048 / 128, 1), 256, GSMEM_256>>>(
        p_xh, p_xl, p_wqh, p_qkv, nullptr, nullptr,
        2048, 2048, 2048, 6144, 0, 0, 0, 1.0f, nullptr);

    // 2) QK RMSNorm + RoPE + V transpose
    qknorm_rope<<<dim3(LEN, NH), HD>>>(pe, q_sc, k_sc);

    // 3) S = scale * Q K^T per head : [H, 2048, 2048] fp32
    gemm_nt_h2<256, 64><<<dim3(2048 / 256, 2048 / 128, NH), 256, GSMEM_256>>>(
        p_qh, p_ql, p_kh, p_s, nullptr, nullptr,
        HD, HD, HD, 2048,
        (long long)LEN * HD, (long long)LEN * HD, (long long)LEN * LEN,
        SCALE, nullptr);

    // 4) row softmax -> fp16 hi/lo probs
    softmax_rows<<<NH * LEN, 256>>>();

    // 5) O = P @ V per head -> fp16 hi/lo into [L, H*D] at column h*128
    gemm_nt_h2<128, 32><<<dim3(HD / 128, 2048 / 128, NH), 256, GSMEM_128>>>(
        p_ph, p_pl, p_vth, nullptr, p_oh, p_ol,
        2048, 2048, 2048, 2048,
        (long long)LEN * LEN, (long long)HD * LEN, (long long)HD,
        1.0f, nullptr);

    // 6) out = O @ w_proj^T + b_proj : [2048, 2048] fp32
    gemm_nt_h2<256, 64><<<dim3(2048 / 256, 2048 / 128, 1), 256, GSMEM_256>>>(
        p_oh, p_ol, p_wph, out, nullptr, nullptr,
        2048, 2048, 2048, 2048, 0, 0, 0, 1.0f, b_proj);
}

// round 8
// speedup vs baseline: 1.8424x; 1.2034x over previous
#include <cuda_runtime.h>
#include <cuda_fp16.h>
#include <math.h>
#include <stdint.h>

#define LEN 2048
#define DIM 2048
#define NH 16
#define HD 128
#define SCALE 0.08838834764831845f  /* 1/sqrt(128) */

// ---------------- scratch (allocation-free: __device__ globals) ----------------
__device__ float g_qkv[(size_t)LEN * 3 * DIM];               // [L, 3*DIM] fp32

__device__ __half g_xh[(size_t)LEN * DIM];                   // x hi/lo (A of QKV)
__device__ __half g_xl[(size_t)LEN * DIM];
__device__ __half g_wqh[(size_t)3 * DIM * DIM];              // w_qkv (B, hi only)
__device__ __half g_wph[(size_t)DIM * DIM];                  // w_proj (B, hi only)
__device__ __half g_qh[(size_t)NH * LEN * HD];               // q*SCALE hi/lo [H,L,D]
__device__ __half g_ql[(size_t)NH * LEN * HD];
__device__ __half g_kh[(size_t)NH * LEN * HD];               // k (hi only) [H,L,D]
__device__ __half g_vth[(size_t)NH * HD * LEN];              // v^T (hi only) [H,D,L]
__device__ __half g_oh[(size_t)LEN * DIM];                   // O hi/lo [L, H*D]
__device__ __half g_ol[(size_t)LEN * DIM];

// ---------------- helpers ----------------
static __device__ __forceinline__ unsigned cvta_smem(const void* p) {
    return (unsigned)__cvta_generic_to_shared(p);
}
static __device__ __forceinline__ unsigned pack2h(float x0, float x1) {
    __half2 h = __floats2half2_rn(x0, x1);
    return *reinterpret_cast<unsigned*>(&h);
}
static __device__ __forceinline__ void split2h(float x0, float x1,
                                               unsigned& hi, unsigned& lo) {
    __half2 h = __floats2half2_rn(x0, x1);
    float2 f = __half22float2(h);
    __half2 l = __floats2half2_rn(x0 - f.x, x1 - f.y);
    hi = *reinterpret_cast<unsigned*>(&h);
    lo = *reinterpret_cast<unsigned*>(&l);
}

#define LDSM4(r0, r1, r2, r3, addr)                                         \
    asm volatile("ldmatrix.sync.aligned.m8n8.x4.shared.b16 {%0,%1,%2,%3}, [%4];" \
                 : "=r"(r0), "=r"(r1), "=r"(r2), "=r"(r3) : "r"(addr))

#define MMA16816(d, a, b0_, b1_)                                            \
    asm volatile("mma.sync.aligned.m16n8k16.row.col.f32.f16.f16.f32 "      \
                 "{%0,%1,%2,%3},{%4,%5,%6,%7},{%8,%9},{%0,%1,%2,%3};"      \
                 : "+f"(d[0]), "+f"(d[1]), "+f"(d[2]), "+f"(d[3])           \
                 : "r"(a[0]), "r"(a[1]), "r"(a[2]), "r"(a[3]),              \
                   "r"(b0_), "r"(b1_))

#define CP_ASYNC16(dst, src) \
    asm volatile("cp.async.cg.shared.global [%0], [%1], 16;" \
                 :: "r"(dst), "l"(src) : "memory")
#define CP_COMMIT() asm volatile("cp.async.commit_group;" ::: "memory")
#define CP_WAIT1()  asm volatile("cp.async.wait_group 1;" ::: "memory")
#define CP_WAIT0()  asm volatile("cp.async.wait_group 0;" ::: "memory")

// ================= generic fp16 NT GEMM (A split, B single) ====================
// loads one ROWSx64 fp16 tile into swizzled smem (128B pitch), 256 threads
template<int ROWS>
static __device__ __forceinline__ void load_tile(
    unsigned sbase, const __half* __restrict__ A,
    int ld, int kbase, int tid)
{
#pragma unroll
    for (int i = 0; i < ROWS / 32; ++i) {
        const int idx = tid + i * 256;
        const int row = idx >> 3;
        const int ch  = idx & 7;
        const unsigned dst = sbase + row * 128 + ((ch * 16) ^ ((row & 7) * 16));
        const __half* src = A + (long long)row * ld + kbase + ch * 8;
        CP_ASYNC16(dst, src);
    }
}

template<int BN, int WN>
__global__ __launch_bounds__(256, 1)
void gemm_nt_h2(const __half* __restrict__ Ah,
                const __half* __restrict__ Al,
                const __half* __restrict__ Bh,
                float* __restrict__ Cf,
                int K, int lda, int ldb, int ldc,
                float alpha, const float* __restrict__ bias)
{
    constexpr int NT16  = WN / 16;
    constexpr int AT    = 128 * 64 * 2;
    constexpr int BT    = BN * 64 * 2;
    constexpr int STAGE = 2 * AT + BT;

    extern __shared__ char smem[];
    const unsigned smem_b = cvta_smem(smem);

    const int tid  = threadIdx.x;
    const int wid  = tid >> 5;
    const int lane = tid & 31;
    const int wm = (wid >> 2) * 64;
    const int wn = (wid & 3) * WN;
    const int m0 = blockIdx.y * 128;
    const int n0 = blockIdx.x * BN;

    const __half* pAh = Ah + (long long)m0 * lda;
    const __half* pAl = Al + (long long)m0 * lda;
    const __half* pBh = Bh + (long long)n0 * ldb;

    unsigned offA0[4], mskA[4];
    const unsigned cbA = ((lane >> 4) & 1) * 16;
#pragma unroll
    for (int mt = 0; mt < 4; ++mt) {
        const int r = wm + mt * 16 + (lane & 15);
        offA0[mt] = r * 128;
        mskA[mt]  = (r & 7) * 16;
    }
    unsigned offB0[NT16], mskB[NT16];
    const unsigned cbB = ((lane >> 3) & 1) * 16;
#pragma unroll
    for (int p = 0; p < NT16; ++p) {
        const int r = wn + p * 16 + (lane & 7) + ((lane >> 4) & 1) * 8;
        offB0[p] = r * 128;
        mskB[p]  = (r & 7) * 16;
    }

    float acc[4][2 * NT16][4];
#pragma unroll
    for (int i = 0; i < 4; ++i)
#pragma unroll
        for (int j = 0; j < 2 * NT16; ++j)
#pragma unroll
            for (int v = 0; v < 4; ++v) acc[i][j][v] = 0.0f;

    const int nch = K >> 6;

    load_tile<128>(smem_b,          pAh, lda, 0, tid);
    load_tile<128>(smem_b + AT,     pAl, lda, 0, tid);
    load_tile<BN> (smem_b + 2 * AT, pBh, ldb, 0, tid);
    CP_COMMIT();

    for (int c = 0; c < nch; ++c) {
        if (c + 1 < nch) {
            const unsigned sb = smem_b + ((c + 1) & 1) * STAGE;
            const int kb = (c + 1) * 64;
            load_tile<128>(sb,          pAh, lda, kb, tid);
            load_tile<128>(sb + AT,     pAl, lda, kb, tid);
            load_tile<BN> (sb + 2 * AT, pBh, ldb, kb, tid);
            CP_COMMIT();
            CP_WAIT1();
        } else {
            CP_WAIT0();
        }
        __syncthreads();

        const unsigned sb = smem_b + (c & 1) * STAGE;
#pragma unroll
        for (int ks = 0; ks < 4; ++ks) {
            const unsigned kb = ks * 32;
            unsigned ah[4][4], al[4][4];
#pragma unroll
            for (int mt = 0; mt < 4; ++mt) {
                const unsigned a0 = sb + offA0[mt] + ((cbA + kb) ^ mskA[mt]);
                LDSM4(ah[mt][0], ah[mt][1], ah[mt][2], ah[mt][3], a0);
                LDSM4(al[mt][0], al[mt][1], al[mt][2], al[mt][3], a0 + AT);
            }
#pragma unroll
            for (int p = 0; p < NT16; ++p) {
                const unsigned b0 = sb + 2 * AT + offB0[p] + ((cbB + kb) ^ mskB[p]);
                unsigned bh[4];
                LDSM4(bh[0], bh[1], bh[2], bh[3], b0);
#pragma unroll
                for (int mt = 0; mt < 4; ++mt) {
                    MMA16816(acc[mt][2 * p],     ah[mt], bh[0], bh[1]);
                    MMA16816(acc[mt][2 * p + 1], ah[mt], bh[2], bh[3]);
                    MMA16816(acc[mt][2 * p],     al[mt], bh[0], bh[1]);
                    MMA16816(acc[mt][2 * p + 1], al[mt], bh[2], bh[3]);
                }
            }
        }
        __syncthreads();
    }

    const int g  = lane >> 2;
    const int tg = lane & 3;
#pragma unroll
    for (int mt = 0; mt < 4; ++mt) {
#pragma unroll
        for (int nt = 0; nt < 2 * NT16; ++nt) {
            const int r = m0 + wm + mt * 16 + g;
            const int c = n0 + wn + nt * 8 + tg * 2;
            float bx = 0.0f, by = 0.0f;
            if (bias) { bx = bias[c]; by = bias[c + 1]; }
            *reinterpret_cast<float2*>(&Cf[(long long)r * ldc + c]) =
                make_float2(acc[mt][nt][0] * alpha + bx, acc[mt][nt][1] * alpha + by);
            *reinterpret_cast<float2*>(&Cf[(long long)(r + 8) * ldc + c]) =
                make_float2(acc[mt][nt][2] * alpha + bx, acc[mt][nt][3] * alpha + by);
        }
    }
}

#define GSMEM_256 (2 * (2 * 16384 + 256 * 64 * 2))   /* 131072 */

// ================= flash attention =================
// grid (16 q-blocks, 16 heads), 256 threads (8 warps), each warp owns 16 q rows.
// smem: Qh 32K | Ql 32K | K 2x32K | V 2x32K = 192KB. Tiles are 128x128 fp16,
// 256B pitch, swizzle: byte = row*256 + ((ch*16) ^ ((row&7)*16)), ch = col/8.
#define FA_SMEM (192 * 1024)

// load 128x128 fp16 tile (256B pitch, swizzled), 256 threads, ld in elements
static __device__ __forceinline__ void fa_load(
    unsigned dst, const __half* __restrict__ src, int ld, int tid)
{
#pragma unroll
    for (int i = 0; i < 8; ++i) {
        const int idx = tid + i * 256;
        const int row = idx >> 4;
        const int ch  = idx & 15;
        const unsigned d = dst + row * 256 + ((ch * 16) ^ ((row & 7) * 16));
        CP_ASYNC16(d, src + (long long)row * ld + ch * 8);
    }
}

__global__ __launch_bounds__(256, 1)
void flash_attn()
{
    extern __shared__ char smem[];
    const unsigned sb  = cvta_smem(smem);
    const unsigned sQh = sb;
    const unsigned sQl = sb + 32768;
    const unsigned sK  = sb + 65536;    // + (j&1)*32768
    const unsigned sV  = sb + 131072;   // + (j&1)*32768

    const int tid  = threadIdx.x;
    const int wid  = tid >> 5;
    const int lane = tid & 31;
    const int qb = blockIdx.x;
    const int h  = blockIdx.y;

    const __half* Qh = g_qh + ((size_t)h * LEN + qb * 128) * HD;
    const __half* Ql = g_ql + ((size_t)h * LEN + qb * 128) * HD;
    const __half* Kh = g_kh + (size_t)h * LEN * HD;
    const __half* Vt = g_vth + (size_t)h * HD * LEN;

    // prologue: Q + (K,V) block 0, then (K,V) block 1
    fa_load(sQh, Qh, HD, tid);
    fa_load(sQl, Ql, HD, tid);
    fa_load(sK, Kh, HD, tid);
    fa_load(sV, Vt, LEN, tid);
    CP_COMMIT();
    fa_load(sK + 32768, Kh + 128 * HD, HD, tid);
    fa_load(sV + 32768, Vt + 128, LEN, tid);
    CP_COMMIT();

    // fragment address components
    const int q0 = wid * 16;
    const unsigned rowA256 = (q0 + (lane & 15)) * 256;       // Q rows
    const unsigned mskA    = (lane & 7) * 16;
    const unsigned caA     = ((lane >> 4) & 1) * 16;
    const int rB0          = (lane & 7) + ((lane >> 4) & 1) * 8;  // B rows base
    const unsigned rowB256 = rB0 * 256;
    const unsigned mskB    = (rB0 & 7) * 16;
    const unsigned cbB     = ((lane >> 3) & 1) * 16;

    float o[16][4];
#pragma unroll
    for (int i = 0; i < 16; ++i)
#pragma unroll
        for (int v = 0; v < 4; ++v) o[i][v] = 0.0f;
    float m0 = -INFINITY, m1 = -INFINITY, l0 = 0.0f, l1 = 0.0f;

    const int NB = LEN / 128;   // 16 key blocks
    for (int j = 0; j < NB; ++j) {
        if (j + 1 < NB) { CP_WAIT1(); } else { CP_WAIT0(); }
        __syncthreads();

        const unsigned kbuf = sK + (j & 1) * 32768;
        const unsigned vbuf = sV + (j & 1) * 32768;

        // ---- S = (Qh+Ql) @ K^T (SCALE pre-folded into Q) ----
        float s[16][4];
#pragma unroll
        for (int i = 0; i < 16; ++i)
#pragma unroll
            for (int v = 0; v < 4; ++v) s[i][v] = 0.0f;

#pragma unroll
        for (int kd = 0; kd < 8; ++kd) {
            const unsigned ca = (kd * 32 + caA) ^ mskA;
            unsigned aqh[4], aql[4];
            LDSM4(aqh[0], aqh[1], aqh[2], aqh[3], sQh + rowA256 + ca);
            LDSM4(aql[0], aql[1], aql[2], aql[3], sQl + rowA256 + ca);
            const unsigned cb = (kd * 32 + cbB) ^ mskB;
#pragma unroll
            for (int p = 0; p < 8; ++p) {
                unsigned bk[4];
                LDSM4(bk[0], bk[1], bk[2], bk[3], kbuf + rowB256 + p * 4096 + cb);
                MMA16816(s[2 * p],     aqh, bk[0], bk[1]);
                MMA16816(s[2 * p + 1], aqh, bk[2], bk[3]);
                MMA16816(s[2 * p],     aql, bk[0], bk[1]);
                MMA16816(s[2 * p + 1], aql, bk[2], bk[3]);
            }
        }

        // ---- online softmax (rows r and r+8 per thread) ----
        float mx0 = -INFINITY, mx1 = -INFINITY;
#pragma unroll
        for (int nt = 0; nt < 16; ++nt) {
            mx0 = fmaxf(mx0, fmaxf(s[nt][0], s[nt][1]));
            mx1 = fmaxf(mx1, fmaxf(s[nt][2], s[nt][3]));
        }
        mx0 = fmaxf(mx0, __shfl_xor_sync(0xffffffffu, mx0, 1));
        mx0 = fmaxf(mx0, __shfl_xor_sync(0xffffffffu, mx0, 2));
        mx1 = fmaxf(mx1, __shfl_xor_sync(0xffffffffu, mx1, 1));
        mx1 = fmaxf(mx1, __shfl_xor_sync(0xffffffffu, mx1, 2));

        const float mn0 = fmaxf(m0, mx0);
        const float mn1 = fmaxf(m1, mx1);
        const float f0 = __expf(m0 - mn0);
        const float f1 = __expf(m1 - mn1);
        m0 = mn0; m1 = mn1;

        float ps0 = 0.0f, ps1 = 0.0f;
#pragma unroll
        for (int nt = 0; nt < 16; ++nt) {
            s[nt][0] = __expf(s[nt][0] - m0); ps0 += s[nt][0];
            s[nt][1] = __expf(s[nt][1] - m0); ps0 += s[nt][1];
            s[nt][2] = __expf(s[nt][2] - m1); ps1 += s[nt][2];
            s[nt][3] = __expf(s[nt][3] - m1); ps1 += s[nt][3];
        }
        l0 = l0 * f0 + ps0;
        l1 = l1 * f1 + ps1;
#pragma unroll
        for (int nt = 0; nt < 16; ++nt) {
            o[nt][0] *= f0; o[nt][1] *= f0;
            o[nt][2] *= f1; o[nt][3] *= f1;
        }

        // ---- O += (Ph+Pl) @ V^T ----
#pragma unroll
        for (int kt = 0; kt < 8; ++kt) {
            unsigned ah[4], al[4];
            split2h(s[2 * kt][0],     s[2 * kt][1],     ah[0], al[0]);
            split2h(s[2 * kt][2],     s[2 * kt][3],     ah[1], al[1]);
            split2h(s[2 * kt + 1][0], s[2 * kt + 1][1], ah[2], al[2]);
            split2h(s[2 * kt + 1][2], s[2 * kt + 1][3], ah[3], al[3]);
            const unsigned cb = (kt * 32 + cbB) ^ mskB;
#pragma unroll
            for (int dt = 0; dt < 8; ++dt) {
                unsigned bv[4];
                LDSM4(bv[0], bv[1], bv[2], bv[3], vbuf + rowB256 + dt * 4096 + cb);
                MMA16816(o[2 * dt],     ah, bv[0], bv[1]);
                MMA16816(o[2 * dt + 1], ah, bv[2], bv[3]);
                MMA16816(o[2 * dt],     al, bv[0], bv[1]);
                MMA16816(o[2 * dt + 1], al, bv[2], bv[3]);
            }
        }

        __syncthreads();
        if (j + 2 < NB) {
            const unsigned kb2 = sK + (j & 1) * 32768;
            const unsigned vb2 = sV + (j & 1) * 32768;
            fa_load(kb2, Kh + (long long)(j + 2) * 128 * HD, HD, tid);
            fa_load(vb2, Vt + (j + 2) * 128, LEN, tid);
            CP_COMMIT();
        }
    }

    // ---- epilogue: normalize, split hi/lo, store [L, H*D] ----
    l0 += __shfl_xor_sync(0xffffffffu, l0, 1);
    l0 += __shfl_xor_sync(0xffffffffu, l0, 2);
    l1 += __shfl_xor_sync(0xffffffffu, l1, 1);
    l1 += __shfl_xor_sync(0xffffffffu, l1, 2);
    const float inv0 = 1.0f / l0;
    const float inv1 = 1.0f / l1;

    const int r0g = qb * 128 + q0 + (lane >> 2);
#pragma unroll
    for (int nt = 0; nt < 16; ++nt) {
        const int d = nt * 8 + (lane & 3) * 2;
        const size_t i0 = (size_t)r0g * DIM + h * HD + d;
        const size_t i1 = i0 + (size_t)8 * DIM;
        unsigned hh, ll;
        split2h(o[nt][0] * inv0, o[nt][1] * inv0, hh, ll);
        *reinterpret_cast<unsigned*>(&g_oh[i0]) = hh;
        *reinterpret_cast<unsigned*>(&g_ol[i0]) = ll;
        split2h(o[nt][2] * inv1, o[nt][3] * inv1, hh, ll);
        *reinterpret_cast<unsigned*>(&g_oh[i1]) = hh;
        *reinterpret_cast<unsigned*>(&g_ol[i1]) = ll;
    }
}

// ---------------- pre-split x; round w_qkv / w_proj to fp16 ----------------
#define SEG_X  (LEN * DIM / 4)
#define SEG_WQ (3 * DIM * DIM / 4)
#define SEG_WP (DIM * DIM / 4)
__global__ void split_inputs(const float* __restrict__ x,
                             const float* __restrict__ wq,
                             const float* __restrict__ wp)
{
    const int i = blockIdx.x * blockDim.x + threadIdx.x;
    if (i < SEG_X) {
        float4 v = reinterpret_cast<const float4*>(x)[i];
        unsigned h0, l0, h1, l1;
        split2h(v.x, v.y, h0, l0);
        split2h(v.z, v.w, h1, l1);
        reinterpret_cast<uint2*>(g_xh)[i] = make_uint2(h0, h1);
        reinterpret_cast<uint2*>(g_xl)[i] = make_uint2(l0, l1);
    } else if (i < SEG_X + SEG_WQ) {
        const int j = i - SEG_X;
        float4 v = reinterpret_cast<const float4*>(wq)[j];
        reinterpret_cast<uint2*>(g_wqh)[j] =
            make_uint2(pack2h(v.x, v.y), pack2h(v.z, v.w));
    } else if (i < SEG_X + SEG_WQ + SEG_WP) {
        const int j = i - SEG_X - SEG_WQ;
        float4 v = reinterpret_cast<const float4*>(wp)[j];
        reinterpret_cast<uint2*>(g_wph)[j] =
            make_uint2(pack2h(v.x, v.y), pack2h(v.z, v.w));
    }
}

// ---------------- QK RMSNorm + RoPE + V transpose ----------------
__global__ void qknorm_rope(const float* __restrict__ pe,
                            const float* __restrict__ qs,
                            const float* __restrict__ ks)
{
    const int l = blockIdx.x;
    const int h = blockIdx.y;
    const int d = threadIdx.x;

    const float* base = g_qkv + (size_t)l * (3 * DIM) + h * HD;
    float q = base[d];
    float k = base[DIM + d];
    float v = base[2 * DIM + d];

    float sq = q * q, sk = k * k;
#pragma unroll
    for (int o = 16; o; o >>= 1) {
        sq += __shfl_xor_sync(0xffffffffu, sq, o);
        sk += __shfl_xor_sync(0xffffffffu, sk, o);
    }
    __shared__ float rq[4], rk[4];
    const int w = d >> 5;
    if ((d & 31) == 0) { rq[w] = sq; rk[w] = sk; }
    __syncthreads();
    sq = rq[0] + rq[1] + rq[2] + rq[3];
    sk = rk[0] + rk[1] + rk[2] + rk[3];

    const float rrq = rsqrtf(sq * (1.0f / HD) + 1e-6f);
    const float rrk = rsqrtf(sk * (1.0f / HD) + 1e-6f);
    float qn = q * rrq * qs[d];
    float kn = k * rrk * ks[d];

    const float qp = __shfl_xor_sync(0xffffffffu, qn, 1);
    const float kp = __shfl_xor_sync(0xffffffffu, kn, 1);
    const int j = d >> 1, a = d & 1;
    const float* p = pe + (size_t)l * (HD / 2) * 4 + j * 4 + a * 2;
    const float q0 = a ? qp : qn, q1 = a ? qn : qp;
    const float k0 = a ? kp : kn, k1 = a ? kn : kp;
    const float qr = (p[0] * q0 + p[1] * q1) * SCALE;  // fold softmax scale into Q
    const float kr = p[0] * k0 + p[1] * k1;

    const size_t idx = ((size_t)h * LEN + l) * HD + d;
    __half qh = __float2half_rn(qr);
    g_qh[idx] = qh;
    g_ql[idx] = __float2half_rn(qr - __half2float(qh));
    g_kh[idx] = __float2half_rn(kr);
    g_vth[((size_t)h * HD + d) * LEN + l] = __float2half_rn(v);
}

// ---------------- launch ----------------
extern "C" void kernel_launch(void* const* d_in, const int* in_sizes, int n_in,
                              void* d_out, int out_size)
{
    const float* x      = (const float*)d_in[0];
    const float* pe     = (const float*)d_in[1];
    const float* w_qkv  = (const float*)d_in[2];
    const float* q_sc   = (const float*)d_in[3];
    const float* k_sc   = (const float*)d_in[4];
    const float* w_proj = (const float*)d_in[5];
    const float* b_proj = (const float*)d_in[6];
    float* out = (float*)d_out;

    float* p_qkv;
    __half *p_xh, *p_xl, *p_wqh, *p_wph, *p_oh, *p_ol;
    cudaGetSymbolAddress((void**)&p_qkv, g_qkv);
    cudaGetSymbolAddress((void**)&p_xh,  g_xh);
    cudaGetSymbolAddress((void**)&p_xl,  g_xl);
    cudaGetSymbolAddress((void**)&p_wqh, g_wqh);
    cudaGetSymbolAddress((void**)&p_wph, g_wph);
    cudaGetSymbolAddress((void**)&p_oh,  g_oh);
    cudaGetSymbolAddress((void**)&p_ol,  g_ol);

    cudaFuncSetAttribute(gemm_nt_h2<256, 64>,
                         cudaFuncAttributeMaxDynamicSharedMemorySize, GSMEM_256);
    cudaFuncSetAttribute(flash_attn,
                         cudaFuncAttributeMaxDynamicSharedMemorySize, FA_SMEM);

    // 0) pre-split x; round weights
    {
        const int total = SEG_X + SEG_WQ + SEG_WP;
        split_inputs<<<(total + 255) / 256, 256>>>(x, w_qkv, w_proj);
    }

    // 1) QKV = x @ w_qkv^T : [2048, 6144] fp32
    gemm_nt_h2<256, 64><<<dim3(6144 / 256, 2048 / 128, 1), 256, GSMEM_256>>>(
        p_xh, p_xl, p_wqh, p_qkv, 2048, 2048, 2048, 6144, 1.0f, nullptr);

    // 2) QK RMSNorm + RoPE + V transpose (SCALE folded into Q)
    qknorm_rope<<<dim3(LEN, NH), HD>>>(pe, q_sc, k_sc);

    // 3) fused attention: S -> online softmax -> O, fp16 hi/lo O output
    flash_attn<<<dim3(LEN / 128, NH), 256, FA_SMEM>>>();

    // 4) out = O @ w_proj^T + b_proj : [2048, 2048] fp32
    gemm_nt_h2<256, 64><<<dim3(2048 / 256, 2048 / 128, 1), 256, GSMEM_256>>>(
        p_oh, p_ol, p_wph, out, 2048, 2048, 2048, 2048, 1.0f, b_proj);
}

// round 9
// speedup vs baseline: 2.2440x; 1.2179x over previous
#include <cuda_runtime.h>
#include <cuda_fp16.h>
#include <math.h>
#include <stdint.h>

#define LEN 2048
#define DIM 2048
#define NH 16
#define HD 128
#define SCALE 0.08838834764831845f  /* 1/sqrt(128) */

// ---------------- scratch (allocation-free: __device__ globals) ----------------
__device__ float g_qkv[(size_t)LEN * 3 * DIM];               // [L, 3*DIM] fp32

__device__ __half g_xh[(size_t)LEN * DIM];                   // x (fp16, hi only)
__device__ __half g_wqh[(size_t)3 * DIM * DIM];              // w_qkv (hi only)
__device__ __half g_wph[(size_t)DIM * DIM];                  // w_proj (hi only)
__device__ __half g_qh[(size_t)NH * LEN * HD];               // q*SCALE hi/lo [H,L,D]
__device__ __half g_ql[(size_t)NH * LEN * HD];
__device__ __half g_kh[(size_t)NH * LEN * HD];               // k (hi only) [H,L,D]
__device__ __half g_vth[(size_t)NH * HD * LEN];              // v^T (hi only) [H,D,L]
__device__ __half g_oh[(size_t)LEN * DIM];                   // O hi/lo [L, H*D]
__device__ __half g_ol[(size_t)LEN * DIM];

// ---------------- helpers ----------------
static __device__ __forceinline__ unsigned cvta_smem(const void* p) {
    return (unsigned)__cvta_generic_to_shared(p);
}
static __device__ __forceinline__ unsigned pack2h(float x0, float x1) {
    __half2 h = __floats2half2_rn(x0, x1);
    return *reinterpret_cast<unsigned*>(&h);
}
static __device__ __forceinline__ void split2h(float x0, float x1,
                                               unsigned& hi, unsigned& lo) {
    __half2 h = __floats2half2_rn(x0, x1);
    float2 f = __half22float2(h);
    __half2 l = __floats2half2_rn(x0 - f.x, x1 - f.y);
    hi = *reinterpret_cast<unsigned*>(&h);
    lo = *reinterpret_cast<unsigned*>(&l);
}

#define LDSM4(r0, r1, r2, r3, addr)                                         \
    asm volatile("ldmatrix.sync.aligned.m8n8.x4.shared.b16 {%0,%1,%2,%3}, [%4];" \
                 : "=r"(r0), "=r"(r1), "=r"(r2), "=r"(r3) : "r"(addr))

#define MMA16816(d, a, b0_, b1_)                                            \
    asm volatile("mma.sync.aligned.m16n8k16.row.col.f32.f16.f16.f32 "      \
                 "{%0,%1,%2,%3},{%4,%5,%6,%7},{%8,%9},{%0,%1,%2,%3};"      \
                 : "+f"(d[0]), "+f"(d[1]), "+f"(d[2]), "+f"(d[3])           \
                 : "r"(a[0]), "r"(a[1]), "r"(a[2]), "r"(a[3]),              \
                   "r"(b0_), "r"(b1_))

#define CP_ASYNC16(dst, src) \
    asm volatile("cp.async.cg.shared.global [%0], [%1], 16;" \
                 :: "r"(dst), "l"(src) : "memory")
#define CP_COMMIT() asm volatile("cp.async.commit_group;" ::: "memory")
#define CP_WAIT1()  asm volatile("cp.async.wait_group 1;" ::: "memory")
#define CP_WAIT0()  asm volatile("cp.async.wait_group 0;" ::: "memory")

// ================= generic fp16 NT GEMM =================
// loads one ROWSx64 fp16 tile into swizzled smem (128B pitch), 256 threads
template<int ROWS>
static __device__ __forceinline__ void load_tile(
    unsigned sbase, const __half* __restrict__ A,
    int ld, int kbase, int tid)
{
#pragma unroll
    for (int i = 0; i < ROWS / 32; ++i) {
        const int idx = tid + i * 256;
        const int row = idx >> 3;
        const int ch  = idx & 7;
        const unsigned dst = sbase + row * 128 + ((ch * 16) ^ ((row & 7) * 16));
        const __half* src = A + (long long)row * ld + kbase + ch * 8;
        CP_ASYNC16(dst, src);
    }
}

// C = alpha*(Ah[+Al]) @ Bh^T (+bias). CTA tile 128xBN, 256 threads,
// 8 warps 2(m)x4(n), warp tile 64xWN, BK=64, 3-stage cp.async, 1 sync/chunk.
template<int BN, int WN, bool SPLIT>
__global__ __launch_bounds__(256, 1)
void gemm_nt_h2(const __half* __restrict__ Ah,
                const __half* __restrict__ Al,
                const __half* __restrict__ Bh,
                float* __restrict__ Cf,
                int K, int lda, int ldb, int ldc,
                float alpha, const float* __restrict__ bias)
{
    constexpr int NT16  = WN / 16;
    constexpr int AT    = 128 * 64 * 2;
    constexpr int BT    = BN * 64 * 2;
    constexpr int NA    = SPLIT ? 2 : 1;
    constexpr int STAGE = NA * AT + BT;

    extern __shared__ char smem[];
    const unsigned smem_b = cvta_smem(smem);

    const int tid  = threadIdx.x;
    const int wid  = tid >> 5;
    const int lane = tid & 31;
    const int wm = (wid >> 2) * 64;
    const int wn = (wid & 3) * WN;
    const int m0 = blockIdx.y * 128;
    const int n0 = blockIdx.x * BN;

    const __half* pAh = Ah + (long long)m0 * lda;
    const __half* pAl = SPLIT ? (Al + (long long)m0 * lda) : nullptr;
    const __half* pBh = Bh + (long long)n0 * ldb;

    unsigned offA0[4], mskA[4];
    const unsigned cbA = ((lane >> 4) & 1) * 16;
#pragma unroll
    for (int mt = 0; mt < 4; ++mt) {
        const int r = wm + mt * 16 + (lane & 15);
        offA0[mt] = r * 128;
        mskA[mt]  = (r & 7) * 16;
    }
    unsigned offB0[NT16], mskB[NT16];
    const unsigned cbB = ((lane >> 3) & 1) * 16;
#pragma unroll
    for (int p = 0; p < NT16; ++p) {
        const int r = wn + p * 16 + (lane & 7) + ((lane >> 4) & 1) * 8;
        offB0[p] = r * 128;
        mskB[p]  = (r & 7) * 16;
    }

    float acc[4][2 * NT16][4];
#pragma unroll
    for (int i = 0; i < 4; ++i)
#pragma unroll
        for (int j = 0; j < 2 * NT16; ++j)
#pragma unroll
            for (int v = 0; v < 4; ++v) acc[i][j][v] = 0.0f;

    const int nch = K >> 6;

    // prologue: stages 0 and 1
#pragma unroll
    for (int pc = 0; pc < 2; ++pc) {
        const unsigned sb = smem_b + pc * STAGE;
        const int kb = pc * 64;
        load_tile<128>(sb, pAh, lda, kb, tid);
        if (SPLIT) load_tile<128>(sb + AT, pAl, lda, kb, tid);
        load_tile<BN>(sb + NA * AT, pBh, ldb, kb, tid);
        CP_COMMIT();
    }

    for (int c = 0; c < nch; ++c) {
        if (c + 1 < nch) { CP_WAIT1(); } else { CP_WAIT0(); }
        __syncthreads();

        // issue prefetch for c+2 (buffer (c+2)%3 == (c-1)%3, safe after sync)
        if (c + 2 < nch) {
            const unsigned sb2 = smem_b + ((c + 2) % 3) * STAGE;
            const int kb = (c + 2) * 64;
            load_tile<128>(sb2, pAh, lda, kb, tid);
            if (SPLIT) load_tile<128>(sb2 + AT, pAl, lda, kb, tid);
            load_tile<BN>(sb2 + NA * AT, pBh, ldb, kb, tid);
            CP_COMMIT();
        }

        const unsigned sb = smem_b + (c % 3) * STAGE;
#pragma unroll
        for (int ks = 0; ks < 4; ++ks) {
            const unsigned kb = ks * 32;
            unsigned ah[4][4], al[4][4];
#pragma unroll
            for (int mt = 0; mt < 4; ++mt) {
                const unsigned a0 = sb + offA0[mt] + ((cbA + kb) ^ mskA[mt]);
                LDSM4(ah[mt][0], ah[mt][1], ah[mt][2], ah[mt][3], a0);
                if (SPLIT)
                    LDSM4(al[mt][0], al[mt][1], al[mt][2], al[mt][3], a0 + AT);
            }
#pragma unroll
            for (int p = 0; p < NT16; ++p) {
                const unsigned b0 = sb + NA * AT + offB0[p] + ((cbB + kb) ^ mskB[p]);
                unsigned bh[4];
                LDSM4(bh[0], bh[1], bh[2], bh[3], b0);
#pragma unroll
                for (int mt = 0; mt < 4; ++mt) {
                    MMA16816(acc[mt][2 * p],     ah[mt], bh[0], bh[1]);
                    MMA16816(acc[mt][2 * p + 1], ah[mt], bh[2], bh[3]);
                    if (SPLIT) {
                        MMA16816(acc[mt][2 * p],     al[mt], bh[0], bh[1]);
                        MMA16816(acc[mt][2 * p + 1], al[mt], bh[2], bh[3]);
                    }
                }
            }
        }
    }

    const int g  = lane >> 2;
    const int tg = lane & 3;
#pragma unroll
    for (int mt = 0; mt < 4; ++mt) {
#pragma unroll
        for (int nt = 0; nt < 2 * NT16; ++nt) {
            const int r = m0 + wm + mt * 16 + g;
            const int c = n0 + wn + nt * 8 + tg * 2;
            float bx = 0.0f, by = 0.0f;
            if (bias) { bx = bias[c]; by = bias[c + 1]; }
            *reinterpret_cast<float2*>(&Cf[(long long)r * ldc + c]) =
                make_float2(acc[mt][nt][0] * alpha + bx, acc[mt][nt][1] * alpha + by);
            *reinterpret_cast<float2*>(&Cf[(long long)(r + 8) * ldc + c]) =
                make_float2(acc[mt][nt][2] * alpha + bx, acc[mt][nt][3] * alpha + by);
        }
    }
}

#define GSMEM_SPLIT  (3 * (2 * 16384 + 256 * 64 * 2))   /* 196608 */
#define GSMEM_SINGLE (3 * (16384 + 256 * 64 * 2))       /* 147456 */

// ================= flash attention =================
// grid (16 q-blocks, 16 heads), 256 threads (8 warps), each warp owns 16 q rows.
// smem: Qh 32K | Ql 32K | K 2x32K | V 2x32K = 192KB. Tiles are 128x128 fp16,
// 256B pitch, swizzle: byte = row*256 + ((ch*16) ^ ((row&7)*16)), ch = col/8.
#define FA_SMEM (192 * 1024)

static __device__ __forceinline__ void fa_load(
    unsigned dst, const __half* __restrict__ src, int ld, int tid)
{
#pragma unroll
    for (int i = 0; i < 8; ++i) {
        const int idx = tid + i * 256;
        const int row = idx >> 4;
        const int ch  = idx & 15;
        const unsigned d = dst + row * 256 + ((ch * 16) ^ ((row & 7) * 16));
        CP_ASYNC16(d, src + (long long)row * ld + ch * 8);
    }
}

__global__ __launch_bounds__(256, 1)
void flash_attn()
{
    extern __shared__ char smem[];
    const unsigned sb  = cvta_smem(smem);
    const unsigned sQh = sb;
    const unsigned sQl = sb + 32768;
    const unsigned sK  = sb + 65536;
    const unsigned sV  = sb + 131072;

    const int tid  = threadIdx.x;
    const int wid  = tid >> 5;
    const int lane = tid & 31;
    const int qb = blockIdx.x;
    const int h  = blockIdx.y;

    const __half* Qh = g_qh + ((size_t)h * LEN + qb * 128) * HD;
    const __half* Ql = g_ql + ((size_t)h * LEN + qb * 128) * HD;
    const __half* Kh = g_kh + (size_t)h * LEN * HD;
    const __half* Vt = g_vth + (size_t)h * HD * LEN;

    fa_load(sQh, Qh, HD, tid);
    fa_load(sQl, Ql, HD, tid);
    fa_load(sK, Kh, HD, tid);
    fa_load(sV, Vt, LEN, tid);
    CP_COMMIT();
    fa_load(sK + 32768, Kh + 128 * HD, HD, tid);
    fa_load(sV + 32768, Vt + 128, LEN, tid);
    CP_COMMIT();

    const int q0 = wid * 16;
    const unsigned rowA256 = (q0 + (lane & 15)) * 256;
    const unsigned mskA    = (lane & 7) * 16;
    const unsigned caA     = ((lane >> 4) & 1) * 16;
    const int rB0          = (lane & 7) + ((lane >> 4) & 1) * 8;
    const unsigned rowB256 = rB0 * 256;
    const unsigned mskB    = (rB0 & 7) * 16;
    const unsigned cbB     = ((lane >> 3) & 1) * 16;

    float o[16][4];
#pragma unroll
    for (int i = 0; i < 16; ++i)
#pragma unroll
        for (int v = 0; v < 4; ++v) o[i][v] = 0.0f;
    float m0 = -INFINITY, m1 = -INFINITY, l0 = 0.0f, l1 = 0.0f;

    const int NB = LEN / 128;
    for (int j = 0; j < NB; ++j) {
        if (j + 1 < NB) { CP_WAIT1(); } else { CP_WAIT0(); }
        __syncthreads();

        const unsigned kbuf = sK + (j & 1) * 32768;
        const unsigned vbuf = sV + (j & 1) * 32768;

        float s[16][4];
#pragma unroll
        for (int i = 0; i < 16; ++i)
#pragma unroll
            for (int v = 0; v < 4; ++v) s[i][v] = 0.0f;

#pragma unroll
        for (int kd = 0; kd < 8; ++kd) {
            const unsigned ca = (kd * 32 + caA) ^ mskA;
            unsigned aqh[4], aql[4];
            LDSM4(aqh[0], aqh[1], aqh[2], aqh[3], sQh + rowA256 + ca);
            LDSM4(aql[0], aql[1], aql[2], aql[3], sQl + rowA256 + ca);
            const unsigned cb = (kd * 32 + cbB) ^ mskB;
#pragma unroll
            for (int p = 0; p < 8; ++p) {
                unsigned bk[4];
                LDSM4(bk[0], bk[1], bk[2], bk[3], kbuf + rowB256 + p * 4096 + cb);
                MMA16816(s[2 * p],     aqh, bk[0], bk[1]);
                MMA16816(s[2 * p + 1], aqh, bk[2], bk[3]);
                MMA16816(s[2 * p],     aql, bk[0], bk[1]);
                MMA16816(s[2 * p + 1], aql, bk[2], bk[3]);
            }
        }

        float mx0 = -INFINITY, mx1 = -INFINITY;
#pragma unroll
        for (int nt = 0; nt < 16; ++nt) {
            mx0 = fmaxf(mx0, fmaxf(s[nt][0], s[nt][1]));
            mx1 = fmaxf(mx1, fmaxf(s[nt][2], s[nt][3]));
        }
        mx0 = fmaxf(mx0, __shfl_xor_sync(0xffffffffu, mx0, 1));
        mx0 = fmaxf(mx0, __shfl_xor_sync(0xffffffffu, mx0, 2));
        mx1 = fmaxf(mx1, __shfl_xor_sync(0xffffffffu, mx1, 1));
        mx1 = fmaxf(mx1, __shfl_xor_sync(0xffffffffu, mx1, 2));

        const float mn0 = fmaxf(m0, mx0);
        const float mn1 = fmaxf(m1, mx1);
        const float f0 = __expf(m0 - mn0);
        const float f1 = __expf(m1 - mn1);
        m0 = mn0; m1 = mn1;

        float ps0 = 0.0f, ps1 = 0.0f;
#pragma unroll
        for (int nt = 0; nt < 16; ++nt) {
            s[nt][0] = __expf(s[nt][0] - m0); ps0 += s[nt][0];
            s[nt][1] = __expf(s[nt][1] - m0); ps0 += s[nt][1];
            s[nt][2] = __expf(s[nt][2] - m1); ps1 += s[nt][2];
            s[nt][3] = __expf(s[nt][3] - m1); ps1 += s[nt][3];
        }
        l0 = l0 * f0 + ps0;
        l1 = l1 * f1 + ps1;
#pragma unroll
        for (int nt = 0; nt < 16; ++nt) {
            o[nt][0] *= f0; o[nt][1] *= f0;
            o[nt][2] *= f1; o[nt][3] *= f1;
        }

#pragma unroll
        for (int kt = 0; kt < 8; ++kt) {
            unsigned ah[4], al[4];
            split2h(s[2 * kt][0],     s[2 * kt][1],     ah[0], al[0]);
            split2h(s[2 * kt][2],     s[2 * kt][3],     ah[1], al[1]);
            split2h(s[2 * kt + 1][0], s[2 * kt + 1][1], ah[2], al[2]);
            split2h(s[2 * kt + 1][2], s[2 * kt + 1][3], ah[3], al[3]);
            const unsigned cb = (kt * 32 + cbB) ^ mskB;
#pragma unroll
            for (int dt = 0; dt < 8; ++dt) {
                unsigned bv[4];
                LDSM4(bv[0], bv[1], bv[2], bv[3], vbuf + rowB256 + dt * 4096 + cb);
                MMA16816(o[2 * dt],     ah, bv[0], bv[1]);
                MMA16816(o[2 * dt + 1], ah, bv[2], bv[3]);
                MMA16816(o[2 * dt],     al, bv[0], bv[1]);
                MMA16816(o[2 * dt + 1], al, bv[2], bv[3]);
            }
        }

        __syncthreads();
        if (j + 2 < NB) {
            const unsigned kb2 = sK + (j & 1) * 32768;
            const unsigned vb2 = sV + (j & 1) * 32768;
            fa_load(kb2, Kh + (long long)(j + 2) * 128 * HD, HD, tid);
            fa_load(vb2, Vt + (j + 2) * 128, LEN, tid);
            CP_COMMIT();
        }
    }

    l0 += __shfl_xor_sync(0xffffffffu, l0, 1);
    l0 += __shfl_xor_sync(0xffffffffu, l0, 2);
    l1 += __shfl_xor_sync(0xffffffffu, l1, 1);
    l1 += __shfl_xor_sync(0xffffffffu, l1, 2);
    const float inv0 = 1.0f / l0;
    const float inv1 = 1.0f / l1;

    const int r0g = qb * 128 + q0 + (lane >> 2);
#pragma unroll
    for (int nt = 0; nt < 16; ++nt) {
        const int d = nt * 8 + (lane & 3) * 2;
        const size_t i0 = (size_t)r0g * DIM + h * HD + d;
        const size_t i1 = i0 + (size_t)8 * DIM;
        unsigned hh, ll;
        split2h(o[nt][0] * inv0, o[nt][1] * inv0, hh, ll);
        *reinterpret_cast<unsigned*>(&g_oh[i0]) = hh;
        *reinterpret_cast<unsigned*>(&g_ol[i0]) = ll;
        split2h(o[nt][2] * inv1, o[nt][3] * inv1, hh, ll);
        *reinterpret_cast<unsigned*>(&g_oh[i1]) = hh;
        *reinterpret_cast<unsigned*>(&g_ol[i1]) = ll;
    }
}

// ---------------- round x / w_qkv / w_proj to fp16 ----------------
#define SEG_X  (LEN * DIM / 4)
#define SEG_WQ (3 * DIM * DIM / 4)
#define SEG_WP (DIM * DIM / 4)
__global__ void split_inputs(const float* __restrict__ x,
                             const float* __restrict__ wq,
                             const float* __restrict__ wp)
{
    const int i = blockIdx.x * blockDim.x + threadIdx.x;
    if (i < SEG_X) {
        float4 v = reinterpret_cast<const float4*>(x)[i];
        reinterpret_cast<uint2*>(g_xh)[i] =
            make_uint2(pack2h(v.x, v.y), pack2h(v.z, v.w));
    } else if (i < SEG_X + SEG_WQ) {
        const int j = i - SEG_X;
        float4 v = reinterpret_cast<const float4*>(wq)[j];
        reinterpret_cast<uint2*>(g_wqh)[j] =
            make_uint2(pack2h(v.x, v.y), pack2h(v.z, v.w));
    } else if (i < SEG_X + SEG_WQ + SEG_WP) {
        const int j = i - SEG_X - SEG_WQ;
        float4 v = reinterpret_cast<const float4*>(wp)[j];
        reinterpret_cast<uint2*>(g_wph)[j] =
            make_uint2(pack2h(v.x, v.y), pack2h(v.z, v.w));
    }
}

// ---------------- QK RMSNorm + RoPE + V transpose ----------------
__global__ void qknorm_rope(const float* __restrict__ pe,
                            const float* __restrict__ qs,
                            const float* __restrict__ ks)
{
    const int l = blockIdx.x;
    const int h = blockIdx.y;
    const int d = threadIdx.x;

    const float* base = g_qkv + (size_t)l * (3 * DIM) + h * HD;
    float q = base[d];
    float k = base[DIM + d];
    float v = base[2 * DIM + d];

    float sq = q * q, sk = k * k;
#pragma unroll
    for (int o = 16; o; o >>= 1) {
        sq += __shfl_xor_sync(0xffffffffu, sq, o);
        sk += __shfl_xor_sync(0xffffffffu, sk, o);
    }
    __shared__ float rq[4], rk[4];
    const int w = d >> 5;
    if ((d & 31) == 0) { rq[w] = sq; rk[w] = sk; }
    __syncthreads();
    sq = rq[0] + rq[1] + rq[2] + rq[3];
    sk = rk[0] + rk[1] + rk[2] + rk[3];

    const float rrq = rsqrtf(sq * (1.0f / HD) + 1e-6f);
    const float rrk = rsqrtf(sk * (1.0f / HD) + 1e-6f);
    float qn = q * rrq * qs[d];
    float kn = k * rrk * ks[d];

    const float qp = __shfl_xor_sync(0xffffffffu, qn, 1);
    const float kp = __shfl_xor_sync(0xffffffffu, kn, 1);
    const int j = d >> 1, a = d & 1;
    const float* p = pe + (size_t)l * (HD / 2) * 4 + j * 4 + a * 2;
    const float q0 = a ? qp : qn, q1 = a ? qn : qp;
    const float k0 = a ? kp : kn, k1 = a ? kn : kp;
    const float qr = (p[0] * q0 + p[1] * q1) * SCALE;
    const float kr = p[0] * k0 + p[1] * k1;

    const size_t idx = ((size_t)h * LEN + l) * HD + d;
    __half qh = __float2half_rn(qr);
    g_qh[idx] = qh;
    g_ql[idx] = __float2half_rn(qr - __half2float(qh));
    g_kh[idx] = __float2half_rn(kr);
    g_vth[((size_t)h * HD + d) * LEN + l] = __float2half_rn(v);
}

// ---------------- launch ----------------
extern "C" void kernel_launch(void* const* d_in, const int* in_sizes, int n_in,
                              void* d_out, int out_size)
{
    const float* x      = (const float*)d_in[0];
    const float* pe     = (const float*)d_in[1];
    const float* w_qkv  = (const float*)d_in[2];
    const float* q_sc   = (const float*)d_in[3];
    const float* k_sc   = (const float*)d_in[4];
    const float* w_proj = (const float*)d_in[5];
    const float* b_proj = (const float*)d_in[6];
    float* out = (float*)d_out;

    float* p_qkv;
    __half *p_xh, *p_wqh, *p_wph, *p_oh, *p_ol;
    cudaGetSymbolAddress((void**)&p_qkv, g_qkv);
    cudaGetSymbolAddress((void**)&p_xh,  g_xh);
    cudaGetSymbolAddress((void**)&p_wqh, g_wqh);
    cudaGetSymbolAddress((void**)&p_wph, g_wph);
    cudaGetSymbolAddress((void**)&p_oh,  g_oh);
    cudaGetSymbolAddress((void**)&p_ol,  g_ol);

    cudaFuncSetAttribute((const void*)gemm_nt_h2<256, 64, false>,
                         cudaFuncAttributeMaxDynamicSharedMemorySize, GSMEM_SINGLE);
    cudaFuncSetAttribute((const void*)gemm_nt_h2<256, 64, true>,
                         cudaFuncAttributeMaxDynamicSharedMemorySize, GSMEM_SPLIT);
    cudaFuncSetAttribute((const void*)flash_attn,
                         cudaFuncAttributeMaxDynamicSharedMemorySize, FA_SMEM);

    // 0) round x, weights to fp16
    {
        const int total = SEG_X + SEG_WQ + SEG_WP;
        split_inputs<<<(total + 255) / 256, 256>>>(x, w_qkv, w_proj);
    }

    // 1) QKV = x @ w_qkv^T : [2048, 6144] fp32 (single-term A)
    gemm_nt_h2<256, 64, false><<<dim3(6144 / 256, 2048 / 128, 1), 256, GSMEM_SINGLE>>>(
        p_xh, nullptr, p_wqh, p_qkv, 2048, 2048, 2048, 6144, 1.0f, nullptr);

    // 2) QK RMSNorm + RoPE + V transpose (SCALE folded into Q)
    qknorm_rope<<<dim3(LEN, NH), HD>>>(pe, q_sc, k_sc);

    // 3) fused attention
    flash_attn<<<dim3(LEN / 128, NH), 256, FA_SMEM>>>();

    // 4) out = (Oh+Ol) @ w_proj^T + b_proj : [2048, 2048] fp32
    gemm_nt_h2<256, 64, true><<<dim3(2048 / 256, 2048 / 128, 1), 256, GSMEM_SPLIT>>>(
        p_oh, p_ol, p_wph, out, 2048, 2048, 2048, 2048, 1.0f, b_proj);
}

// round 10
// speedup vs baseline: 2.6897x; 1.1986x over previous
#include <cuda_runtime.h>
#include <cuda_fp16.h>
#include <math.h>
#include <stdint.h>

#define LEN 2048
#define DIM 2048
#define NH 16
#define HD 128
#define SCALE 0.08838834764831845f  /* 1/sqrt(128) */

// ---------------- scratch (allocation-free: __device__ globals) ----------------
__device__ float g_qkv[(size_t)LEN * 3 * DIM];               // [L, 3*DIM] fp32

__device__ __half g_xh[(size_t)LEN * DIM];                   // x (fp16)
__device__ __half g_wqh[(size_t)3 * DIM * DIM];              // w_qkv (fp16)
__device__ __half g_wph[(size_t)DIM * DIM];                  // w_proj (fp16)
__device__ __half g_qh[(size_t)NH * LEN * HD];               // q*SCALE hi/lo [H,L,D]
__device__ __half g_ql[(size_t)NH * LEN * HD];
__device__ __half g_kh[(size_t)NH * LEN * HD];               // k (fp16) [H,L,D]
__device__ __half g_vth[(size_t)NH * HD * LEN];              // v^T (fp16) [H,D,L]
__device__ __half g_oh[(size_t)LEN * DIM];                   // O (fp16) [L, H*D]

// ---------------- helpers ----------------
static __device__ __forceinline__ unsigned cvta_smem(const void* p) {
    return (unsigned)__cvta_generic_to_shared(p);
}
static __device__ __forceinline__ unsigned pack2h(float x0, float x1) {
    __half2 h = __floats2half2_rn(x0, x1);
    return *reinterpret_cast<unsigned*>(&h);
}
static __device__ __forceinline__ void split2h(float x0, float x1,
                                               unsigned& hi, unsigned& lo) {
    __half2 h = __floats2half2_rn(x0, x1);
    float2 f = __half22float2(h);
    __half2 l = __floats2half2_rn(x0 - f.x, x1 - f.y);
    hi = *reinterpret_cast<unsigned*>(&h);
    lo = *reinterpret_cast<unsigned*>(&l);
}

#define LDSM4(r0, r1, r2, r3, addr)                                         \
    asm volatile("ldmatrix.sync.aligned.m8n8.x4.shared.b16 {%0,%1,%2,%3}, [%4];" \
                 : "=r"(r0), "=r"(r1), "=r"(r2), "=r"(r3) : "r"(addr))

#define MMA16816(d, a, b0_, b1_)                                            \
    asm volatile("mma.sync.aligned.m16n8k16.row.col.f32.f16.f16.f32 "      \
                 "{%0,%1,%2,%3},{%4,%5,%6,%7},{%8,%9},{%0,%1,%2,%3};"      \
                 : "+f"(d[0]), "+f"(d[1]), "+f"(d[2]), "+f"(d[3])           \
                 : "r"(a[0]), "r"(a[1]), "r"(a[2]), "r"(a[3]),              \
                   "r"(b0_), "r"(b1_))

#define CP_ASYNC16(dst, src) \
    asm volatile("cp.async.cg.shared.global [%0], [%1], 16;" \
                 :: "r"(dst), "l"(src) : "memory")
#define CP_COMMIT() asm volatile("cp.async.commit_group;" ::: "memory")
#define CP_WAIT1()  asm volatile("cp.async.wait_group 1;" ::: "memory")
#define CP_WAIT0()  asm volatile("cp.async.wait_group 0;" ::: "memory")

// ================= generic fp16 NT GEMM =================
template<int ROWS>
static __device__ __forceinline__ void load_tile(
    unsigned sbase, const __half* __restrict__ A,
    int ld, int kbase, int tid)
{
#pragma unroll
    for (int i = 0; i < ROWS / 32; ++i) {
        const int idx = tid + i * 256;
        const int row = idx >> 3;
        const int ch  = idx & 7;
        const unsigned dst = sbase + row * 128 + ((ch * 16) ^ ((row & 7) * 16));
        const __half* src = A + (long long)row * ld + kbase + ch * 8;
        CP_ASYNC16(dst, src);
    }
}

// C = alpha*(Ah[+Al]) @ Bh^T (+bias). CTA tile 128xBN, 256 threads,
// 8 warps 2(m)x4(n), warp tile 64xWN, BK=64, 3-stage cp.async, 1 sync/chunk.
template<int BN, int WN, bool SPLIT>
__global__ __launch_bounds__(256, 1)
void gemm_nt_h2(const __half* __restrict__ Ah,
                const __half* __restrict__ Al,
                const __half* __restrict__ Bh,
                float* __restrict__ Cf,
                int K, int lda, int ldb, int ldc,
                float alpha, const float* __restrict__ bias)
{
    constexpr int NT16  = WN / 16;
    constexpr int AT    = 128 * 64 * 2;
    constexpr int BT    = BN * 64 * 2;
    constexpr int NA    = SPLIT ? 2 : 1;
    constexpr int STAGE = NA * AT + BT;

    extern __shared__ char smem[];
    const unsigned smem_b = cvta_smem(smem);

    const int tid  = threadIdx.x;
    const int wid  = tid >> 5;
    const int lane = tid & 31;
    const int wm = (wid >> 2) * 64;
    const int wn = (wid & 3) * WN;
    const int m0 = blockIdx.y * 128;
    const int n0 = blockIdx.x * BN;

    const __half* pAh = Ah + (long long)m0 * lda;
    const __half* pAl = SPLIT ? (Al + (long long)m0 * lda) : nullptr;
    const __half* pBh = Bh + (long long)n0 * ldb;

    unsigned offA0[4], mskA[4];
    const unsigned cbA = ((lane >> 4) & 1) * 16;
#pragma unroll
    for (int mt = 0; mt < 4; ++mt) {
        const int r = wm + mt * 16 + (lane & 15);
        offA0[mt] = r * 128;
        mskA[mt]  = (r & 7) * 16;
    }
    unsigned offB0[NT16], mskB[NT16];
    const unsigned cbB = ((lane >> 3) & 1) * 16;
#pragma unroll
    for (int p = 0; p < NT16; ++p) {
        const int r = wn + p * 16 + (lane & 7) + ((lane >> 4) & 1) * 8;
        offB0[p] = r * 128;
        mskB[p]  = (r & 7) * 16;
    }

    float acc[4][2 * NT16][4];
#pragma unroll
    for (int i = 0; i < 4; ++i)
#pragma unroll
        for (int j = 0; j < 2 * NT16; ++j)
#pragma unroll
            for (int v = 0; v < 4; ++v) acc[i][j][v] = 0.0f;

    const int nch = K >> 6;

#pragma unroll
    for (int pc = 0; pc < 2; ++pc) {
        const unsigned sb = smem_b + pc * STAGE;
        const int kb = pc * 64;
        load_tile<128>(sb, pAh, lda, kb, tid);
        if (SPLIT) load_tile<128>(sb + AT, pAl, lda, kb, tid);
        load_tile<BN>(sb + NA * AT, pBh, ldb, kb, tid);
        CP_COMMIT();
    }

    for (int c = 0; c < nch; ++c) {
        if (c + 1 < nch) { CP_WAIT1(); } else { CP_WAIT0(); }
        __syncthreads();

        if (c + 2 < nch) {
            const unsigned sb2 = smem_b + ((c + 2) % 3) * STAGE;
            const int kb = (c + 2) * 64;
            load_tile<128>(sb2, pAh, lda, kb, tid);
            if (SPLIT) load_tile<128>(sb2 + AT, pAl, lda, kb, tid);
            load_tile<BN>(sb2 + NA * AT, pBh, ldb, kb, tid);
            CP_COMMIT();
        }

        const unsigned sb = smem_b + (c % 3) * STAGE;
#pragma unroll
        for (int ks = 0; ks < 4; ++ks) {
            const unsigned kb = ks * 32;
            unsigned ah[4][4], al[4][4];
#pragma unroll
            for (int mt = 0; mt < 4; ++mt) {
                const unsigned a0 = sb + offA0[mt] + ((cbA + kb) ^ mskA[mt]);
                LDSM4(ah[mt][0], ah[mt][1], ah[mt][2], ah[mt][3], a0);
                if (SPLIT)
                    LDSM4(al[mt][0], al[mt][1], al[mt][2], al[mt][3], a0 + AT);
            }
#pragma unroll
            for (int p = 0; p < NT16; ++p) {
                const unsigned b0 = sb + NA * AT + offB0[p] + ((cbB + kb) ^ mskB[p]);
                unsigned bh[4];
                LDSM4(bh[0], bh[1], bh[2], bh[3], b0);
#pragma unroll
                for (int mt = 0; mt < 4; ++mt) {
                    MMA16816(acc[mt][2 * p],     ah[mt], bh[0], bh[1]);
                    MMA16816(acc[mt][2 * p + 1], ah[mt], bh[2], bh[3]);
                    if (SPLIT) {
                        MMA16816(acc[mt][2 * p],     al[mt], bh[0], bh[1]);
                        MMA16816(acc[mt][2 * p + 1], al[mt], bh[2], bh[3]);
                    }
                }
            }
        }
    }

    const int g  = lane >> 2;
    const int tg = lane & 3;
#pragma unroll
    for (int mt = 0; mt < 4; ++mt) {
#pragma unroll
        for (int nt = 0; nt < 2 * NT16; ++nt) {
            const int r = m0 + wm + mt * 16 + g;
            const int c = n0 + wn + nt * 8 + tg * 2;
            float bx = 0.0f, by = 0.0f;
            if (bias) { bx = bias[c]; by = bias[c + 1]; }
            *reinterpret_cast<float2*>(&Cf[(long long)r * ldc + c]) =
                make_float2(acc[mt][nt][0] * alpha + bx, acc[mt][nt][1] * alpha + by);
            *reinterpret_cast<float2*>(&Cf[(long long)(r + 8) * ldc + c]) =
                make_float2(acc[mt][nt][2] * alpha + bx, acc[mt][nt][3] * alpha + by);
        }
    }
}

#define GSMEM_SINGLE (3 * (16384 + 256 * 64 * 2))       /* 147456 */

// ================= flash attention =================
// grid (16 q-blocks, 16 heads), 256 threads (8 warps), each warp owns 16 q rows.
// smem: Qh 32K | Ql 32K | K 2x32K | V 2x32K = 192KB. Tiles 128x128 fp16,
// 256B pitch, swizzle: byte = row*256 + ((ch*16) ^ ((row&7)*16)), ch = col/8.
#define FA_SMEM (192 * 1024)

static __device__ __forceinline__ void fa_load(
    unsigned dst, const __half* __restrict__ src, int ld, int tid)
{
#pragma unroll
    for (int i = 0; i < 8; ++i) {
        const int idx = tid + i * 256;
        const int row = idx >> 4;
        const int ch  = idx & 15;
        const unsigned d = dst + row * 256 + ((ch * 16) ^ ((row & 7) * 16));
        CP_ASYNC16(d, src + (long long)row * ld + ch * 8);
    }
}

__global__ __launch_bounds__(256, 1)
void flash_attn()
{
    extern __shared__ char smem[];
    const unsigned sb  = cvta_smem(smem);
    const unsigned sQh = sb;
    const unsigned sQl = sb + 32768;
    const unsigned sK  = sb + 65536;
    const unsigned sV  = sb + 131072;

    const int tid  = threadIdx.x;
    const int wid  = tid >> 5;
    const int lane = tid & 31;
    const int qb = blockIdx.x;
    const int h  = blockIdx.y;

    const __half* Qh = g_qh + ((size_t)h * LEN + qb * 128) * HD;
    const __half* Ql = g_ql + ((size_t)h * LEN + qb * 128) * HD;
    const __half* Kh = g_kh + (size_t)h * LEN * HD;
    const __half* Vt = g_vth + (size_t)h * HD * LEN;

    fa_load(sQh, Qh, HD, tid);
    fa_load(sQl, Ql, HD, tid);
    fa_load(sK, Kh, HD, tid);
    fa_load(sV, Vt, LEN, tid);
    CP_COMMIT();
    fa_load(sK + 32768, Kh + 128 * HD, HD, tid);
    fa_load(sV + 32768, Vt + 128, LEN, tid);
    CP_COMMIT();

    const int q0 = wid * 16;
    const unsigned rowA256 = (q0 + (lane & 15)) * 256;
    const unsigned mskA    = (lane & 7) * 16;
    const unsigned caA     = ((lane >> 4) & 1) * 16;
    const int rB0          = (lane & 7) + ((lane >> 4) & 1) * 8;
    const unsigned rowB256 = rB0 * 256;
    const unsigned mskB    = (rB0 & 7) * 16;
    const unsigned cbB     = ((lane >> 3) & 1) * 16;

    float o[16][4];
#pragma unroll
    for (int i = 0; i < 16; ++i)
#pragma unroll
        for (int v = 0; v < 4; ++v) o[i][v] = 0.0f;
    float m0 = -INFINITY, m1 = -INFINITY, l0 = 0.0f, l1 = 0.0f;

    const int NB = LEN / 128;
    for (int j = 0; j < NB; ++j) {
        if (j + 1 < NB) { CP_WAIT1(); } else { CP_WAIT0(); }
        __syncthreads();

        const unsigned kbuf = sK + (j & 1) * 32768;
        const unsigned vbuf = sV + (j & 1) * 32768;

        // ---- S = (Qh+Ql) @ K^T ----
        float s[16][4];
#pragma unroll
        for (int i = 0; i < 16; ++i)
#pragma unroll
            for (int v = 0; v < 4; ++v) s[i][v] = 0.0f;

#pragma unroll
        for (int kd = 0; kd < 8; ++kd) {
            const unsigned ca = (kd * 32 + caA) ^ mskA;
            unsigned aqh[4], aql[4];
            LDSM4(aqh[0], aqh[1], aqh[2], aqh[3], sQh + rowA256 + ca);
            LDSM4(aql[0], aql[1], aql[2], aql[3], sQl + rowA256 + ca);
            const unsigned cb = (kd * 32 + cbB) ^ mskB;
#pragma unroll
            for (int p = 0; p < 8; ++p) {
                unsigned bk[4];
                LDSM4(bk[0], bk[1], bk[2], bk[3], kbuf + rowB256 + p * 4096 + cb);
                MMA16816(s[2 * p],     aqh, bk[0], bk[1]);
                MMA16816(s[2 * p + 1], aqh, bk[2], bk[3]);
                MMA16816(s[2 * p],     aql, bk[0], bk[1]);
                MMA16816(s[2 * p + 1], aql, bk[2], bk[3]);
            }
        }

        // ---- online softmax ----
        float mx0 = -INFINITY, mx1 = -INFINITY;
#pragma unroll
        for (int nt = 0; nt < 16; ++nt) {
            mx0 = fmaxf(mx0, fmaxf(s[nt][0], s[nt][1]));
            mx1 = fmaxf(mx1, fmaxf(s[nt][2], s[nt][3]));
        }
        mx0 = fmaxf(mx0, __shfl_xor_sync(0xffffffffu, mx0, 1));
        mx0 = fmaxf(mx0, __shfl_xor_sync(0xffffffffu, mx0, 2));
        mx1 = fmaxf(mx1, __shfl_xor_sync(0xffffffffu, mx1, 1));
        mx1 = fmaxf(mx1, __shfl_xor_sync(0xffffffffu, mx1, 2));

        const float mn0 = fmaxf(m0, mx0);
        const float mn1 = fmaxf(m1, mx1);
        const float f0 = __expf(m0 - mn0);
        const float f1 = __expf(m1 - mn1);
        m0 = mn0; m1 = mn1;

        float ps0 = 0.0f, ps1 = 0.0f;
#pragma unroll
        for (int nt = 0; nt < 16; ++nt) {
            s[nt][0] = __expf(s[nt][0] - m0); ps0 += s[nt][0];
            s[nt][1] = __expf(s[nt][1] - m0); ps0 += s[nt][1];
            s[nt][2] = __expf(s[nt][2] - m1); ps1 += s[nt][2];
            s[nt][3] = __expf(s[nt][3] - m1); ps1 += s[nt][3];
        }
        l0 = l0 * f0 + ps0;
        l1 = l1 * f1 + ps1;
#pragma unroll
        for (int nt = 0; nt < 16; ++nt) {
            o[nt][0] *= f0; o[nt][1] *= f0;
            o[nt][2] *= f1; o[nt][3] *= f1;
        }

        // ---- O += P @ V^T (P single fp16) ----
#pragma unroll
        for (int kt = 0; kt < 8; ++kt) {
            unsigned ah[4];
            ah[0] = pack2h(s[2 * kt][0],     s[2 * kt][1]);
            ah[1] = pack2h(s[2 * kt][2],     s[2 * kt][3]);
            ah[2] = pack2h(s[2 * kt + 1][0], s[2 * kt + 1][1]);
            ah[3] = pack2h(s[2 * kt + 1][2], s[2 * kt + 1][3]);
            const unsigned cb = (kt * 32 + cbB) ^ mskB;
#pragma unroll
            for (int dt = 0; dt < 8; ++dt) {
                unsigned bv[4];
                LDSM4(bv[0], bv[1], bv[2], bv[3], vbuf + rowB256 + dt * 4096 + cb);
                MMA16816(o[2 * dt],     ah, bv[0], bv[1]);
                MMA16816(o[2 * dt + 1], ah, bv[2], bv[3]);
            }
        }

        __syncthreads();
        if (j + 2 < NB) {
            const unsigned kb2 = sK + (j & 1) * 32768;
            const unsigned vb2 = sV + (j & 1) * 32768;
            fa_load(kb2, Kh + (long long)(j + 2) * 128 * HD, HD, tid);
            fa_load(vb2, Vt + (j + 2) * 128, LEN, tid);
            CP_COMMIT();
        }
    }

    // ---- epilogue: normalize, store fp16 O [L, H*D] ----
    l0 += __shfl_xor_sync(0xffffffffu, l0, 1);
    l0 += __shfl_xor_sync(0xffffffffu, l0, 2);
    l1 += __shfl_xor_sync(0xffffffffu, l1, 1);
    l1 += __shfl_xor_sync(0xffffffffu, l1, 2);
    const float inv0 = 1.0f / l0;
    const float inv1 = 1.0f / l1;

    const int r0g = qb * 128 + q0 + (lane >> 2);
#pragma unroll
    for (int nt = 0; nt < 16; ++nt) {
        const int d = nt * 8 + (lane & 3) * 2;
        const size_t i0 = (size_t)r0g * DIM + h * HD + d;
        const size_t i1 = i0 + (size_t)8 * DIM;
        *reinterpret_cast<unsigned*>(&g_oh[i0]) =
            pack2h(o[nt][0] * inv0, o[nt][1] * inv0);
        *reinterpret_cast<unsigned*>(&g_oh[i1]) =
            pack2h(o[nt][2] * inv1, o[nt][3] * inv1);
    }
}

// ---------------- round x / w_qkv / w_proj to fp16 ----------------
#define SEG_X  (LEN * DIM / 4)
#define SEG_WQ (3 * DIM * DIM / 4)
#define SEG_WP (DIM * DIM / 4)
__global__ void split_inputs(const float* __restrict__ x,
                             const float* __restrict__ wq,
                             const float* __restrict__ wp)
{
    const int i = blockIdx.x * blockDim.x + threadIdx.x;
    if (i < SEG_X) {
        float4 v = reinterpret_cast<const float4*>(x)[i];
        reinterpret_cast<uint2*>(g_xh)[i] =
            make_uint2(pack2h(v.x, v.y), pack2h(v.z, v.w));
    } else if (i < SEG_X + SEG_WQ) {
        const int j = i - SEG_X;
        float4 v = reinterpret_cast<const float4*>(wq)[j];
        reinterpret_cast<uint2*>(g_wqh)[j] =
            make_uint2(pack2h(v.x, v.y), pack2h(v.z, v.w));
    } else if (i < SEG_X + SEG_WQ + SEG_WP) {
        const int j = i - SEG_X - SEG_WQ;
        float4 v = reinterpret_cast<const float4*>(wp)[j];
        reinterpret_cast<uint2*>(g_wph)[j] =
            make_uint2(pack2h(v.x, v.y), pack2h(v.z, v.w));
    }
}

// ---------------- QK RMSNorm + RoPE + V transpose ----------------
__global__ void qknorm_rope(const float* __restrict__ pe,
                            const float* __restrict__ qs,
                            const float* __restrict__ ks)
{
    const int l = blockIdx.x;
    const int h = blockIdx.y;
    const int d = threadIdx.x;

    const float* base = g_qkv + (size_t)l * (3 * DIM) + h * HD;
    float q = base[d];
    float k = base[DIM + d];
    float v = base[2 * DIM + d];

    float sq = q * q, sk = k * k;
#pragma unroll
    for (int o = 16; o; o >>= 1) {
        sq += __shfl_xor_sync(0xffffffffu, sq, o);
        sk += __shfl_xor_sync(0xffffffffu, sk, o);
    }
    __shared__ float rq[4], rk[4];
    const int w = d >> 5;
    if ((d & 31) == 0) { rq[w] = sq; rk[w] = sk; }
    __syncthreads();
    sq = rq[0] + rq[1] + rq[2] + rq[3];
    sk = rk[0] + rk[1] + rk[2] + rk[3];

    const float rrq = rsqrtf(sq * (1.0f / HD) + 1e-6f);
    const float rrk = rsqrtf(sk * (1.0f / HD) + 1e-6f);
    float qn = q * rrq * qs[d];
    float kn = k * rrk * ks[d];

    const float qp = __shfl_xor_sync(0xffffffffu, qn, 1);
    const float kp = __shfl_xor_sync(0xffffffffu, kn, 1);
    const int j = d >> 1, a = d & 1;
    const float* p = pe + (size_t)l * (HD / 2) * 4 + j * 4 + a * 2;
    const float q0 = a ? qp : qn, q1 = a ? qn : qp;
    const float k0 = a ? kp : kn, k1 = a ? kn : kp;
    const float qr = (p[0] * q0 + p[1] * q1) * SCALE;
    const float kr = p[0] * k0 + p[1] * k1;

    const size_t idx = ((size_t)h * LEN + l) * HD + d;
    __half qh = __float2half_rn(qr);
    g_qh[idx] = qh;
    g_ql[idx] = __float2half_rn(qr - __half2float(qh));
    g_kh[idx] = __float2half_rn(kr);
    g_vth[((size_t)h * HD + d) * LEN + l] = __float2half_rn(v);
}

// ---------------- launch ----------------
extern "C" void kernel_launch(void* const* d_in, const int* in_sizes, int n_in,
                              void* d_out, int out_size)
{
    const float* x      = (const float*)d_in[0];
    const float* pe     = (const float*)d_in[1];
    const float* w_qkv  = (const float*)d_in[2];
    const float* q_sc   = (const float*)d_in[3];
    const float* k_sc   = (const float*)d_in[4];
    const float* w_proj = (const float*)d_in[5];
    const float* b_proj = (const float*)d_in[6];
    float* out = (float*)d_out;

    float* p_qkv;
    __half *p_xh, *p_wqh, *p_wph, *p_oh;
    cudaGetSymbolAddress((void**)&p_qkv, g_qkv);
    cudaGetSymbolAddress((void**)&p_xh,  g_xh);
    cudaGetSymbolAddress((void**)&p_wqh, g_wqh);
    cudaGetSymbolAddress((void**)&p_wph, g_wph);
    cudaGetSymbolAddress((void**)&p_oh,  g_oh);

    cudaFuncSetAttribute((const void*)gemm_nt_h2<256, 64, false>,
                         cudaFuncAttributeMaxDynamicSharedMemorySize, GSMEM_SINGLE);
    cudaFuncSetAttribute((const void*)flash_attn,
                         cudaFuncAttributeMaxDynamicSharedMemorySize, FA_SMEM);

    // 0) round x, weights to fp16
    {
        const int total = SEG_X + SEG_WQ + SEG_WP;
        split_inputs<<<(total + 255) / 256, 256>>>(x, w_qkv, w_proj);
    }

    // 1) QKV = x @ w_qkv^T : [2048, 6144] fp32
    gemm_nt_h2<256, 64, false><<<dim3(6144 / 256, 2048 / 128, 1), 256, GSMEM_SINGLE>>>(
        p_xh, nullptr, p_wqh, p_qkv, 2048, 2048, 2048, 6144, 1.0f, nullptr);

    // 2) QK RMSNorm + RoPE + V transpose (SCALE folded into Q)
    qknorm_rope<<<dim3(LEN, NH), HD>>>(pe, q_sc, k_sc);

    // 3) fused attention (P and O single fp16)
    flash_attn<<<dim3(LEN / 128, NH), 256, FA_SMEM>>>();

    // 4) out = O @ w_proj^T + b_proj : [2048, 2048] fp32
    gemm_nt_h2<256, 64, false><<<dim3(2048 / 256, 2048 / 128, 1), 256, GSMEM_SINGLE>>>(
        p_oh, nullptr, p_wph, out, 2048, 2048, 2048, 2048, 1.0f, b_proj);
}

// round 11
// speedup vs baseline: 2.9012x; 1.0786x over previous
#include <cuda_runtime.h>
#include <cuda_fp16.h>
#include <math.h>
#include <stdint.h>

#define LEN 2048
#define DIM 2048
#define NH 16
#define HD 128
#define SCALE 0.08838834764831845f  /* 1/sqrt(128) */

// ---------------- scratch (allocation-free: __device__ globals) ----------------
__device__ float g_qkv[(size_t)LEN * 3 * DIM];               // [L, 3*DIM] fp32

__device__ __half g_xh[(size_t)LEN * DIM];                   // x (fp16)
__device__ __half g_wqh[(size_t)3 * DIM * DIM];              // w_qkv (fp16)
__device__ __half g_wph[(size_t)DIM * DIM];                  // w_proj (fp16)
__device__ __half g_qh[(size_t)NH * LEN * HD];               // q*SCALE (fp16) [H,L,D]
__device__ __half g_kh[(size_t)NH * LEN * HD];               // k (fp16) [H,L,D]
__device__ __half g_vth[(size_t)NH * HD * LEN];              // v^T (fp16) [H,D,L]
__device__ __half g_oh[(size_t)LEN * DIM];                   // O (fp16) [L, H*D]

// ---------------- helpers ----------------
static __device__ __forceinline__ unsigned cvta_smem(const void* p) {
    return (unsigned)__cvta_generic_to_shared(p);
}
static __device__ __forceinline__ unsigned pack2h(float x0, float x1) {
    __half2 h = __floats2half2_rn(x0, x1);
    return *reinterpret_cast<unsigned*>(&h);
}

#define LDSM4(r0, r1, r2, r3, addr)                                         \
    asm volatile("ldmatrix.sync.aligned.m8n8.x4.shared.b16 {%0,%1,%2,%3}, [%4];" \
                 : "=r"(r0), "=r"(r1), "=r"(r2), "=r"(r3) : "r"(addr))

#define MMA16816(d, a, b0_, b1_)                                            \
    asm volatile("mma.sync.aligned.m16n8k16.row.col.f32.f16.f16.f32 "      \
                 "{%0,%1,%2,%3},{%4,%5,%6,%7},{%8,%9},{%0,%1,%2,%3};"      \
                 : "+f"(d[0]), "+f"(d[1]), "+f"(d[2]), "+f"(d[3])           \
                 : "r"(a[0]), "r"(a[1]), "r"(a[2]), "r"(a[3]),              \
                   "r"(b0_), "r"(b1_))

#define CP_ASYNC16(dst, src) \
    asm volatile("cp.async.cg.shared.global [%0], [%1], 16;" \
                 :: "r"(dst), "l"(src) : "memory")
#define CP_COMMIT() asm volatile("cp.async.commit_group;" ::: "memory")
#define CP_WAIT1()  asm volatile("cp.async.wait_group 1;" ::: "memory")
#define CP_WAIT0()  asm volatile("cp.async.wait_group 0;" ::: "memory")

// ================= generic fp16 NT GEMM =================
template<int ROWS>
static __device__ __forceinline__ void load_tile(
    unsigned sbase, const __half* __restrict__ A,
    int ld, int kbase, int tid)
{
#pragma unroll
    for (int i = 0; i < ROWS / 32; ++i) {
        const int idx = tid + i * 256;
        const int row = idx >> 3;
        const int ch  = idx & 7;
        const unsigned dst = sbase + row * 128 + ((ch * 16) ^ ((row & 7) * 16));
        const __half* src = A + (long long)row * ld + kbase + ch * 8;
        CP_ASYNC16(dst, src);
    }
}

// C = alpha * A @ B^T (+bias). CTA tile 128xBN, 256 threads,
// 8 warps 2(m)x4(n), warp tile 64xWN, BK=64, 3-stage cp.async, 1 sync/chunk.
template<int BN, int WN>
__global__ __launch_bounds__(256, 1)
void gemm_nt_h2(const __half* __restrict__ Ah,
                const __half* __restrict__ Bh,
                float* __restrict__ Cf,
                int K, int lda, int ldb, int ldc,
                float alpha, const float* __restrict__ bias)
{
    constexpr int NT16  = WN / 16;
    constexpr int AT    = 128 * 64 * 2;
    constexpr int BT    = BN * 64 * 2;
    constexpr int STAGE = AT + BT;

    extern __shared__ char smem[];
    const unsigned smem_b = cvta_smem(smem);

    const int tid  = threadIdx.x;
    const int wid  = tid >> 5;
    const int lane = tid & 31;
    const int wm = (wid >> 2) * 64;
    const int wn = (wid & 3) * WN;
    const int m0 = blockIdx.y * 128;
    const int n0 = blockIdx.x * BN;

    const __half* pAh = Ah + (long long)m0 * lda;
    const __half* pBh = Bh + (long long)n0 * ldb;

    unsigned offA0[4], mskA[4];
    const unsigned cbA = ((lane >> 4) & 1) * 16;
#pragma unroll
    for (int mt = 0; mt < 4; ++mt) {
        const int r = wm + mt * 16 + (lane & 15);
        offA0[mt] = r * 128;
        mskA[mt]  = (r & 7) * 16;
    }
    unsigned offB0[NT16], mskB[NT16];
    const unsigned cbB = ((lane >> 3) & 1) * 16;
#pragma unroll
    for (int p = 0; p < NT16; ++p) {
        const int r = wn + p * 16 + (lane & 7) + ((lane >> 4) & 1) * 8;
        offB0[p] = r * 128;
        mskB[p]  = (r & 7) * 16;
    }

    float acc[4][2 * NT16][4];
#pragma unroll
    for (int i = 0; i < 4; ++i)
#pragma unroll
        for (int j = 0; j < 2 * NT16; ++j)
#pragma unroll
            for (int v = 0; v < 4; ++v) acc[i][j][v] = 0.0f;

    const int nch = K >> 6;

#pragma unroll
    for (int pc = 0; pc < 2; ++pc) {
        const unsigned sb = smem_b + pc * STAGE;
        const int kb = pc * 64;
        load_tile<128>(sb, pAh, lda, kb, tid);
        load_tile<BN>(sb + AT, pBh, ldb, kb, tid);
        CP_COMMIT();
    }

    for (int c = 0; c < nch; ++c) {
        if (c + 1 < nch) { CP_WAIT1(); } else { CP_WAIT0(); }
        __syncthreads();

        if (c + 2 < nch) {
            const unsigned sb2 = smem_b + ((c + 2) % 3) * STAGE;
            const int kb = (c + 2) * 64;
            load_tile<128>(sb2, pAh, lda, kb, tid);
            load_tile<BN>(sb2 + AT, pBh, ldb, kb, tid);
            CP_COMMIT();
        }

        const unsigned sb = smem_b + (c % 3) * STAGE;
#pragma unroll
        for (int ks = 0; ks < 4; ++ks) {
            const unsigned kb = ks * 32;
            unsigned ah[4][4];
#pragma unroll
            for (int mt = 0; mt < 4; ++mt) {
                const unsigned a0 = sb + offA0[mt] + ((cbA + kb) ^ mskA[mt]);
                LDSM4(ah[mt][0], ah[mt][1], ah[mt][2], ah[mt][3], a0);
            }
#pragma unroll
            for (int p = 0; p < NT16; ++p) {
                const unsigned b0 = sb + AT + offB0[p] + ((cbB + kb) ^ mskB[p]);
                unsigned bh[4];
                LDSM4(bh[0], bh[1], bh[2], bh[3], b0);
#pragma unroll
                for (int mt = 0; mt < 4; ++mt) {
                    MMA16816(acc[mt][2 * p],     ah[mt], bh[0], bh[1]);
                    MMA16816(acc[mt][2 * p + 1], ah[mt], bh[2], bh[3]);
                }
            }
        }
    }

    const int g  = lane >> 2;
    const int tg = lane & 3;
#pragma unroll
    for (int mt = 0; mt < 4; ++mt) {
#pragma unroll
        for (int nt = 0; nt < 2 * NT16; ++nt) {
            const int r = m0 + wm + mt * 16 + g;
            const int c = n0 + wn + nt * 8 + tg * 2;
            float bx = 0.0f, by = 0.0f;
            if (bias) { bx = bias[c]; by = bias[c + 1]; }
            *reinterpret_cast<float2*>(&Cf[(long long)r * ldc + c]) =
                make_float2(acc[mt][nt][0] * alpha + bx, acc[mt][nt][1] * alpha + by);
            *reinterpret_cast<float2*>(&Cf[(long long)(r + 8) * ldc + c]) =
                make_float2(acc[mt][nt][2] * alpha + bx, acc[mt][nt][3] * alpha + by);
        }
    }
}

#define GSMEM_SINGLE (3 * (16384 + 256 * 64 * 2))       /* 147456 */

// ================= flash attention =================
// grid (16 q-blocks, 16 heads), 256 threads (8 warps), each warp owns 16 q rows.
// smem: Q 32K | K 2x32K | V 2x32K = 160KB. Tiles 128x128 fp16,
// 256B pitch, swizzle: byte = row*256 + ((ch*16) ^ ((row&7)*16)), ch = col/8.
#define FA_SMEM (160 * 1024)

static __device__ __forceinline__ void fa_load(
    unsigned dst, const __half* __restrict__ src, int ld, int tid)
{
#pragma unroll
    for (int i = 0; i < 8; ++i) {
        const int idx = tid + i * 256;
        const int row = idx >> 4;
        const int ch  = idx & 15;
        const unsigned d = dst + row * 256 + ((ch * 16) ^ ((row & 7) * 16));
        CP_ASYNC16(d, src + (long long)row * ld + ch * 8);
    }
}

__global__ __launch_bounds__(256, 1)
void flash_attn()
{
    extern __shared__ char smem[];
    const unsigned sb  = cvta_smem(smem);
    const unsigned sQ  = sb;
    const unsigned sK  = sb + 32768;    // + (j&1)*32768
    const unsigned sV  = sb + 98304;    // + (j&1)*32768

    const int tid  = threadIdx.x;
    const int wid  = tid >> 5;
    const int lane = tid & 31;
    const int qb = blockIdx.x;
    const int h  = blockIdx.y;

    const __half* Qh = g_qh + ((size_t)h * LEN + qb * 128) * HD;
    const __half* Kh = g_kh + (size_t)h * LEN * HD;
    const __half* Vt = g_vth + (size_t)h * HD * LEN;

    fa_load(sQ, Qh, HD, tid);
    fa_load(sK, Kh, HD, tid);
    fa_load(sV, Vt, LEN, tid);
    CP_COMMIT();
    fa_load(sK + 32768, Kh + 128 * HD, HD, tid);
    fa_load(sV + 32768, Vt + 128, LEN, tid);
    CP_COMMIT();

    const int q0 = wid * 16;
    const unsigned rowA256 = (q0 + (lane & 15)) * 256;
    const unsigned mskA    = (lane & 7) * 16;
    const unsigned caA     = ((lane >> 4) & 1) * 16;
    const int rB0          = (lane & 7) + ((lane >> 4) & 1) * 8;
    const unsigned rowB256 = rB0 * 256;
    const unsigned mskB    = (rB0 & 7) * 16;
    const unsigned cbB     = ((lane >> 3) & 1) * 16;

    float o[16][4];
#pragma unroll
    for (int i = 0; i < 16; ++i)
#pragma unroll
        for (int v = 0; v < 4; ++v) o[i][v] = 0.0f;
    float m0 = -INFINITY, m1 = -INFINITY, l0 = 0.0f, l1 = 0.0f;

    const int NB = LEN / 128;
    for (int j = 0; j < NB; ++j) {
        if (j + 1 < NB) { CP_WAIT1(); } else { CP_WAIT0(); }
        __syncthreads();

        const unsigned kbuf = sK + (j & 1) * 32768;
        const unsigned vbuf = sV + (j & 1) * 32768;

        // ---- S = Q @ K^T (both single fp16) ----
        float s[16][4];
#pragma unroll
        for (int i = 0; i < 16; ++i)
#pragma unroll
            for (int v = 0; v < 4; ++v) s[i][v] = 0.0f;

#pragma unroll
        for (int kd = 0; kd < 8; ++kd) {
            const unsigned ca = (kd * 32 + caA) ^ mskA;
            unsigned aq[4];
            LDSM4(aq[0], aq[1], aq[2], aq[3], sQ + rowA256 + ca);
            const unsigned cb = (kd * 32 + cbB) ^ mskB;
#pragma unroll
            for (int p = 0; p < 8; ++p) {
                unsigned bk[4];
                LDSM4(bk[0], bk[1], bk[2], bk[3], kbuf + rowB256 + p * 4096 + cb);
                MMA16816(s[2 * p],     aq, bk[0], bk[1]);
                MMA16816(s[2 * p + 1], aq, bk[2], bk[3]);
            }
        }

        // ---- online softmax ----
        float mx0 = -INFINITY, mx1 = -INFINITY;
#pragma unroll
        for (int nt = 0; nt < 16; ++nt) {
            mx0 = fmaxf(mx0, fmaxf(s[nt][0], s[nt][1]));
            mx1 = fmaxf(mx1, fmaxf(s[nt][2], s[nt][3]));
        }
        mx0 = fmaxf(mx0, __shfl_xor_sync(0xffffffffu, mx0, 1));
        mx0 = fmaxf(mx0, __shfl_xor_sync(0xffffffffu, mx0, 2));
        mx1 = fmaxf(mx1, __shfl_xor_sync(0xffffffffu, mx1, 1));
        mx1 = fmaxf(mx1, __shfl_xor_sync(0xffffffffu, mx1, 2));

        const float mn0 = fmaxf(m0, mx0);
        const float mn1 = fmaxf(m1, mx1);
        const float f0 = __expf(m0 - mn0);
        const float f1 = __expf(m1 - mn1);
        m0 = mn0; m1 = mn1;

        float ps0 = 0.0f, ps1 = 0.0f;
#pragma unroll
        for (int nt = 0; nt < 16; ++nt) {
            s[nt][0] = __expf(s[nt][0] - m0); ps0 += s[nt][0];
            s[nt][1] = __expf(s[nt][1] - m0); ps0 += s[nt][1];
            s[nt][2] = __expf(s[nt][2] - m1); ps1 += s[nt][2];
            s[nt][3] = __expf(s[nt][3] - m1); ps1 += s[nt][3];
        }
        l0 = l0 * f0 + ps0;
        l1 = l1 * f1 + ps1;
#pragma unroll
        for (int nt = 0; nt < 16; ++nt) {
            o[nt][0] *= f0; o[nt][1] *= f0;
            o[nt][2] *= f1; o[nt][3] *= f1;
        }

        // ---- O += P @ V^T (P single fp16) ----
#pragma unroll
        for (int kt = 0; kt < 8; ++kt) {
            unsigned ah[4];
            ah[0] = pack2h(s[2 * kt][0],     s[2 * kt][1]);
            ah[1] = pack2h(s[2 * kt][2],     s[2 * kt][3]);
            ah[2] = pack2h(s[2 * kt + 1][0], s[2 * kt + 1][1]);
            ah[3] = pack2h(s[2 * kt + 1][2], s[2 * kt + 1][3]);
            const unsigned cb = (kt * 32 + cbB) ^ mskB;
#pragma unroll
            for (int dt = 0; dt < 8; ++dt) {
                unsigned bv[4];
                LDSM4(bv[0], bv[1], bv[2], bv[3], vbuf + rowB256 + dt * 4096 + cb);
                MMA16816(o[2 * dt],     ah, bv[0], bv[1]);
                MMA16816(o[2 * dt + 1], ah, bv[2], bv[3]);
            }
        }

        __syncthreads();
        if (j + 2 < NB) {
            const unsigned kb2 = sK + (j & 1) * 32768;
            const unsigned vb2 = sV + (j & 1) * 32768;
            fa_load(kb2, Kh + (long long)(j + 2) * 128 * HD, HD, tid);
            fa_load(vb2, Vt + (j + 2) * 128, LEN, tid);
            CP_COMMIT();
        }
    }

    // ---- epilogue: normalize, store fp16 O [L, H*D] ----
    l0 += __shfl_xor_sync(0xffffffffu, l0, 1);
    l0 += __shfl_xor_sync(0xffffffffu, l0, 2);
    l1 += __shfl_xor_sync(0xffffffffu, l1, 1);
    l1 += __shfl_xor_sync(0xffffffffu, l1, 2);
    const float inv0 = 1.0f / l0;
    const float inv1 = 1.0f / l1;

    const int r0g = qb * 128 + q0 + (lane >> 2);
#pragma unroll
    for (int nt = 0; nt < 16; ++nt) {
        const int d = nt * 8 + (lane & 3) * 2;
        const size_t i0 = (size_t)r0g * DIM + h * HD + d;
        const size_t i1 = i0 + (size_t)8 * DIM;
        *reinterpret_cast<unsigned*>(&g_oh[i0]) =
            pack2h(o[nt][0] * inv0, o[nt][1] * inv0);
        *reinterpret_cast<unsigned*>(&g_oh[i1]) =
            pack2h(o[nt][2] * inv1, o[nt][3] * inv1);
    }
}

// ---------------- round x / w_qkv / w_proj to fp16 ----------------
#define SEG_X  (LEN * DIM / 4)
#define SEG_WQ (3 * DIM * DIM / 4)
#define SEG_WP (DIM * DIM / 4)
__global__ void split_inputs(const float* __restrict__ x,
                             const float* __restrict__ wq,
                             const float* __restrict__ wp)
{
    const int i = blockIdx.x * blockDim.x + threadIdx.x;
    if (i < SEG_X) {
        float4 v = reinterpret_cast<const float4*>(x)[i];
        reinterpret_cast<uint2*>(g_xh)[i] =
            make_uint2(pack2h(v.x, v.y), pack2h(v.z, v.w));
    } else if (i < SEG_X + SEG_WQ) {
        const int j = i - SEG_X;
        float4 v = reinterpret_cast<const float4*>(wq)[j];
        reinterpret_cast<uint2*>(g_wqh)[j] =
            make_uint2(pack2h(v.x, v.y), pack2h(v.z, v.w));
    } else if (i < SEG_X + SEG_WQ + SEG_WP) {
        const int j = i - SEG_X - SEG_WQ;
        float4 v = reinterpret_cast<const float4*>(wp)[j];
        reinterpret_cast<uint2*>(g_wph)[j] =
            make_uint2(pack2h(v.x, v.y), pack2h(v.z, v.w));
    }
}

// ---------------- QK RMSNorm + RoPE + V transpose ----------------
__global__ void qknorm_rope(const float* __restrict__ pe,
                            const float* __restrict__ qs,
                            const float* __restrict__ ks)
{
    const int l = blockIdx.x;
    const int h = blockIdx.y;
    const int d = threadIdx.x;

    const float* base = g_qkv + (size_t)l * (3 * DIM) + h * HD;
    float q = base[d];
    float k = base[DIM + d];
    float v = base[2 * DIM + d];

    float sq = q * q, sk = k * k;
#pragma unroll
    for (int o = 16; o; o >>= 1) {
        sq += __shfl_xor_sync(0xffffffffu, sq, o);
        sk += __shfl_xor_sync(0xffffffffu, sk, o);
    }
    __shared__ float rq[4], rk[4];
    const int w = d >> 5;
    if ((d & 31) == 0) { rq[w] = sq; rk[w] = sk; }
    __syncthreads();
    sq = rq[0] + rq[1] + rq[2] + rq[3];
    sk = rk[0] + rk[1] + rk[2] + rk[3];

    const float rrq = rsqrtf(sq * (1.0f / HD) + 1e-6f);
    const float rrk = rsqrtf(sk * (1.0f / HD) + 1e-6f);
    float qn = q * rrq * qs[d];
    float kn = k * rrk * ks[d];

    const float qp = __shfl_xor_sync(0xffffffffu, qn, 1);
    const float kp = __shfl_xor_sync(0xffffffffu, kn, 1);
    const int j = d >> 1, a = d & 1;
    const float* p = pe + (size_t)l * (HD / 2) * 4 + j * 4 + a * 2;
    const float q0 = a ? qp : qn, q1 = a ? qn : qp;
    const float k0 = a ? kp : kn, k1 = a ? kn : kp;
    const float qr = (p[0] * q0 + p[1] * q1) * SCALE;
    const float kr = p[0] * k0 + p[1] * k1;

    const size_t idx = ((size_t)h * LEN + l) * HD + d;
    g_qh[idx] = __float2half_rn(qr);
    g_kh[idx] = __float2half_rn(kr);
    g_vth[((size_t)h * HD + d) * LEN + l] = __float2half_rn(v);
}

// ---------------- launch ----------------
extern "C" void kernel_launch(void* const* d_in, const int* in_sizes, int n_in,
                              void* d_out, int out_size)
{
    const float* x      = (const float*)d_in[0];
    const float* pe     = (const float*)d_in[1];
    const float* w_qkv  = (const float*)d_in[2];
    const float* q_sc   = (const float*)d_in[3];
    const float* k_sc   = (const float*)d_in[4];
    const float* w_proj = (const float*)d_in[5];
    const float* b_proj = (const float*)d_in[6];
    float* out = (float*)d_out;

    float* p_qkv;
    __half *p_xh, *p_wqh, *p_wph, *p_oh;
    cudaGetSymbolAddress((void**)&p_qkv, g_qkv);
    cudaGetSymbolAddress((void**)&p_xh,  g_xh);
    cudaGetSymbolAddress((void**)&p_wqh, g_wqh);
    cudaGetSymbolAddress((void**)&p_wph, g_wph);
    cudaGetSymbolAddress((void**)&p_oh,  g_oh);

    cudaFuncSetAttribute((const void*)gemm_nt_h2<256, 64>,
                         cudaFuncAttributeMaxDynamicSharedMemorySize, GSMEM_SINGLE);
    cudaFuncSetAttribute((const void*)flash_attn,
                         cudaFuncAttributeMaxDynamicSharedMemorySize, FA_SMEM);

    // 0) round x, weights to fp16
    {
        const int total = SEG_X + SEG_WQ + SEG_WP;
        split_inputs<<<(total + 255) / 256, 256>>>(x, w_qkv, w_proj);
    }

    // 1) QKV = x @ w_qkv^T : [2048, 6144] fp32
    gemm_nt_h2<256, 64><<<dim3(6144 / 256, 2048 / 128, 1), 256, GSMEM_SINGLE>>>(
        p_xh, p_wqh, p_qkv, 2048, 2048, 2048, 6144, 1.0f, nullptr);

    // 2) QK RMSNorm + RoPE + V transpose (SCALE folded into Q)
    qknorm_rope<<<dim3(LEN, NH), HD>>>(pe, q_sc, k_sc);

    // 3) fused attention (Q, K, V, P, O all single fp16)
    flash_attn<<<dim3(LEN / 128, NH), 256, FA_SMEM>>>();

    // 4) out = O @ w_proj^T + b_proj : [2048, 2048] fp32
    gemm_nt_h2<256, 64><<<dim3(2048 / 256, 2048 / 128, 1), 256, GSMEM_SINGLE>>>(
        p_oh, p_wph, out, 2048, 2048, 2048, 2048, 1.0f, b_proj);
}

// round 12
// speedup vs baseline: 2.9663x; 1.0224x over previous
#include <cuda_runtime.h>
#include <cuda_fp16.h>
#include <math.h>
#include <stdint.h>

#define LEN 2048
#define DIM 2048
#define NH 16
#define HD 128
#define SCALE 0.08838834764831845f   /* 1/sqrt(128) */
#define LOG2E 1.4426950408889634f
#define SOFT_OFF (4.0f * LOG2E)      /* fixed softmax offset, log2 domain */

// ---------------- scratch (allocation-free: __device__ globals) ----------------
__device__ __half g_qkv[(size_t)LEN * 3 * DIM];              // [L, 3*DIM] fp16

__device__ __half g_xh[(size_t)LEN * DIM];                   // x (fp16)
__device__ __half g_wqh[(size_t)3 * DIM * DIM];              // w_qkv (fp16)
__device__ __half g_wph[(size_t)DIM * DIM];                  // w_proj (fp16)
__device__ __half g_qh[(size_t)NH * LEN * HD];               // q*SCALE*log2e [H,L,D]
__device__ __half g_kh[(size_t)NH * LEN * HD];               // k (fp16) [H,L,D]
__device__ __half g_vth[(size_t)NH * HD * LEN];              // v^T (fp16) [H,D,L]
__device__ __half g_oh[(size_t)LEN * DIM];                   // O (fp16) [L, H*D]

// ---------------- helpers ----------------
static __device__ __forceinline__ unsigned cvta_smem(const void* p) {
    return (unsigned)__cvta_generic_to_shared(p);
}
static __device__ __forceinline__ unsigned pack2h(float x0, float x1) {
    __half2 h = __floats2half2_rn(x0, x1);
    return *reinterpret_cast<unsigned*>(&h);
}

#define LDSM4(r0, r1, r2, r3, addr)                                         \
    asm volatile("ldmatrix.sync.aligned.m8n8.x4.shared.b16 {%0,%1,%2,%3}, [%4];" \
                 : "=r"(r0), "=r"(r1), "=r"(r2), "=r"(r3) : "r"(addr))

#define MMA16816(d, a, b0_, b1_)                                            \
    asm volatile("mma.sync.aligned.m16n8k16.row.col.f32.f16.f16.f32 "      \
                 "{%0,%1,%2,%3},{%4,%5,%6,%7},{%8,%9},{%0,%1,%2,%3};"      \
                 : "+f"(d[0]), "+f"(d[1]), "+f"(d[2]), "+f"(d[3])           \
                 : "r"(a[0]), "r"(a[1]), "r"(a[2]), "r"(a[3]),              \
                   "r"(b0_), "r"(b1_))

#define CP_ASYNC16(dst, src) \
    asm volatile("cp.async.cg.shared.global [%0], [%1], 16;" \
                 :: "r"(dst), "l"(src) : "memory")
#define CP_COMMIT() asm volatile("cp.async.commit_group;" ::: "memory")
#define CP_WAIT1()  asm volatile("cp.async.wait_group 1;" ::: "memory")
#define CP_WAIT0()  asm volatile("cp.async.wait_group 0;" ::: "memory")

// ================= generic fp16 NT GEMM =================
template<int ROWS>
static __device__ __forceinline__ void load_tile(
    unsigned sbase, const __half* __restrict__ A,
    int ld, int kbase, int tid)
{
#pragma unroll
    for (int i = 0; i < ROWS / 32; ++i) {
        const int idx = tid + i * 256;
        const int row = idx >> 3;
        const int ch  = idx & 7;
        const unsigned dst = sbase + row * 128 + ((ch * 16) ^ ((row & 7) * 16));
        const __half* src = A + (long long)row * ld + kbase + ch * 8;
        CP_ASYNC16(dst, src);
    }
}

// C = alpha * A @ B^T (+bias). OUT = float or __half.
// CTA tile 128xBN, 256 threads, 8 warps 2(m)x4(n), warp tile 64xWN,
// BK=64, 3-stage cp.async, 1 sync/chunk.
template<int BN, int WN, typename OUT>
__global__ __launch_bounds__(256, 1)
void gemm_nt_h2(const __half* __restrict__ Ah,
                const __half* __restrict__ Bh,
                OUT* __restrict__ C,
                int K, int lda, int ldb, int ldc,
                float alpha, const float* __restrict__ bias)
{
    constexpr int NT16  = WN / 16;
    constexpr int AT    = 128 * 64 * 2;
    constexpr int BT    = BN * 64 * 2;
    constexpr int STAGE = AT + BT;

    extern __shared__ char smem[];
    const unsigned smem_b = cvta_smem(smem);

    const int tid  = threadIdx.x;
    const int wid  = tid >> 5;
    const int lane = tid & 31;
    const int wm = (wid >> 2) * 64;
    const int wn = (wid & 3) * WN;
    const int m0 = blockIdx.y * 128;
    const int n0 = blockIdx.x * BN;

    const __half* pAh = Ah + (long long)m0 * lda;
    const __half* pBh = Bh + (long long)n0 * ldb;

    unsigned offA0[4], mskA[4];
    const unsigned cbA = ((lane >> 4) & 1) * 16;
#pragma unroll
    for (int mt = 0; mt < 4; ++mt) {
        const int r = wm + mt * 16 + (lane & 15);
        offA0[mt] = r * 128;
        mskA[mt]  = (r & 7) * 16;
    }
    unsigned offB0[NT16], mskB[NT16];
    const unsigned cbB = ((lane >> 3) & 1) * 16;
#pragma unroll
    for (int p = 0; p < NT16; ++p) {
        const int r = wn + p * 16 + (lane & 7) + ((lane >> 4) & 1) * 8;
        offB0[p] = r * 128;
        mskB[p]  = (r & 7) * 16;
    }

    float acc[4][2 * NT16][4];
#pragma unroll
    for (int i = 0; i < 4; ++i)
#pragma unroll
        for (int j = 0; j < 2 * NT16; ++j)
#pragma unroll
            for (int v = 0; v < 4; ++v) acc[i][j][v] = 0.0f;

    const int nch = K >> 6;

#pragma unroll
    for (int pc = 0; pc < 2; ++pc) {
        const unsigned sb = smem_b + pc * STAGE;
        const int kb = pc * 64;
        load_tile<128>(sb, pAh, lda, kb, tid);
        load_tile<BN>(sb + AT, pBh, ldb, kb, tid);
        CP_COMMIT();
    }

    for (int c = 0; c < nch; ++c) {
        if (c + 1 < nch) { CP_WAIT1(); } else { CP_WAIT0(); }
        __syncthreads();

        if (c + 2 < nch) {
            const unsigned sb2 = smem_b + ((c + 2) % 3) * STAGE;
            const int kb = (c + 2) * 64;
            load_tile<128>(sb2, pAh, lda, kb, tid);
            load_tile<BN>(sb2 + AT, pBh, ldb, kb, tid);
            CP_COMMIT();
        }

        const unsigned sb = smem_b + (c % 3) * STAGE;
#pragma unroll
        for (int ks = 0; ks < 4; ++ks) {
            const unsigned kb = ks * 32;
            unsigned ah[4][4];
#pragma unroll
            for (int mt = 0; mt < 4; ++mt) {
                const unsigned a0 = sb + offA0[mt] + ((cbA + kb) ^ mskA[mt]);
                LDSM4(ah[mt][0], ah[mt][1], ah[mt][2], ah[mt][3], a0);
            }
#pragma unroll
            for (int p = 0; p < NT16; ++p) {
                const unsigned b0 = sb + AT + offB0[p] + ((cbB + kb) ^ mskB[p]);
                unsigned bh[4];
                LDSM4(bh[0], bh[1], bh[2], bh[3], b0);
#pragma unroll
                for (int mt = 0; mt < 4; ++mt) {
                    MMA16816(acc[mt][2 * p],     ah[mt], bh[0], bh[1]);
                    MMA16816(acc[mt][2 * p + 1], ah[mt], bh[2], bh[3]);
                }
            }
        }
    }

    const int g  = lane >> 2;
    const int tg = lane & 3;
#pragma unroll
    for (int mt = 0; mt < 4; ++mt) {
#pragma unroll
        for (int nt = 0; nt < 2 * NT16; ++nt) {
            const int r = m0 + wm + mt * 16 + g;
            const int c = n0 + wn + nt * 8 + tg * 2;
            float bx = 0.0f, by = 0.0f;
            if (bias) { bx = bias[c]; by = bias[c + 1]; }
            const float v00 = acc[mt][nt][0] * alpha + bx;
            const float v01 = acc[mt][nt][1] * alpha + by;
            const float v10 = acc[mt][nt][2] * alpha + bx;
            const float v11 = acc[mt][nt][3] * alpha + by;
            if (sizeof(OUT) == 4) {
                *reinterpret_cast<float2*>((float*)C + (long long)r * ldc + c) =
                    make_float2(v00, v01);
                *reinterpret_cast<float2*>((float*)C + (long long)(r + 8) * ldc + c) =
                    make_float2(v10, v11);
            } else {
                *reinterpret_cast<unsigned*>((__half*)C + (long long)r * ldc + c) =
                    pack2h(v00, v01);
                *reinterpret_cast<unsigned*>((__half*)C + (long long)(r + 8) * ldc + c) =
                    pack2h(v10, v11);
            }
        }
    }
}

#define GSMEM_SINGLE (3 * (16384 + 256 * 64 * 2))       /* 147456 */

// ================= flash attention =================
// grid (16 q-blocks, 16 heads), 256 threads (8 warps), each warp owns 16 q rows.
// smem: Q 32K | K 2x32K | V 2x32K = 160KB. Tiles 128x128 fp16,
// 256B pitch, swizzle: byte = row*256 + ((ch*16) ^ ((row&7)*16)), ch = col/8.
// No-max softmax: |logit| <= sqrt(128) by QKNorm, offset -4 nats baked into
// the S accumulator init; Q pre-scaled by SCALE*log2e so exp == exp2f.
#define FA_SMEM (160 * 1024)

static __device__ __forceinline__ void fa_load(
    unsigned dst, const __half* __restrict__ src, int ld, int tid)
{
#pragma unroll
    for (int i = 0; i < 8; ++i) {
        const int idx = tid + i * 256;
        const int row = idx >> 4;
        const int ch  = idx & 15;
        const unsigned d = dst + row * 256 + ((ch * 16) ^ ((row & 7) * 16));
        CP_ASYNC16(d, src + (long long)row * ld + ch * 8);
    }
}

__global__ __launch_bounds__(256, 1)
void flash_attn()
{
    extern __shared__ char smem[];
    const unsigned sb  = cvta_smem(smem);
    const unsigned sQ  = sb;
    const unsigned sK  = sb + 32768;
    const unsigned sV  = sb + 98304;

    const int tid  = threadIdx.x;
    const int wid  = tid >> 5;
    const int lane = tid & 31;
    const int qb = blockIdx.x;
    const int h  = blockIdx.y;

    const __half* Qh = g_qh + ((size_t)h * LEN + qb * 128) * HD;
    const __half* Kh = g_kh + (size_t)h * LEN * HD;
    const __half* Vt = g_vth + (size_t)h * HD * LEN;

    fa_load(sQ, Qh, HD, tid);
    fa_load(sK, Kh, HD, tid);
    fa_load(sV, Vt, LEN, tid);
    CP_COMMIT();
    fa_load(sK + 32768, Kh + 128 * HD, HD, tid);
    fa_load(sV + 32768, Vt + 128, LEN, tid);
    CP_COMMIT();

    const int q0 = wid * 16;
    const unsigned rowA256 = (q0 + (lane & 15)) * 256;
    const unsigned mskA    = (lane & 7) * 16;
    const unsigned caA     = ((lane >> 4) & 1) * 16;
    const int rB0          = (lane & 7) + ((lane >> 4) & 1) * 8;
    const unsigned rowB256 = rB0 * 256;
    const unsigned mskB    = (rB0 & 7) * 16;
    const unsigned cbB     = ((lane >> 3) & 1) * 16;

    float o[16][4];
#pragma unroll
    for (int i = 0; i < 16; ++i)
#pragma unroll
        for (int v = 0; v < 4; ++v) o[i][v] = 0.0f;
    float l0 = 0.0f, l1 = 0.0f;

    const int NB = LEN / 128;
    for (int j = 0; j < NB; ++j) {
        if (j + 1 < NB) { CP_WAIT1(); } else { CP_WAIT0(); }
        __syncthreads();

        const unsigned kbuf = sK + (j & 1) * 32768;
        const unsigned vbuf = sV + (j & 1) * 32768;

        // ---- S = Q @ K^T + (-offset), log2 domain ----
        float s[16][4];
#pragma unroll
        for (int i = 0; i < 16; ++i)
#pragma unroll
            for (int v = 0; v < 4; ++v) s[i][v] = -SOFT_OFF;

#pragma unroll
        for (int kd = 0; kd < 8; ++kd) {
            const unsigned ca = (kd * 32 + caA) ^ mskA;
            unsigned aq[4];
            LDSM4(aq[0], aq[1], aq[2], aq[3], sQ + rowA256 + ca);
            const unsigned cb = (kd * 32 + cbB) ^ mskB;
#pragma unroll
            for (int p = 0; p < 8; ++p) {
                unsigned bk[4];
                LDSM4(bk[0], bk[1], bk[2], bk[3], kbuf + rowB256 + p * 4096 + cb);
                MMA16816(s[2 * p],     aq, bk[0], bk[1]);
                MMA16816(s[2 * p + 1], aq, bk[2], bk[3]);
            }
        }

        // ---- exp2 + row-sum accumulate (no max needed) ----
        float ps0 = 0.0f, ps1 = 0.0f;
#pragma unroll
        for (int nt = 0; nt < 16; ++nt) {
            s[nt][0] = exp2f(s[nt][0]); ps0 += s[nt][0];
            s[nt][1] = exp2f(s[nt][1]); ps0 += s[nt][1];
            s[nt][2] = exp2f(s[nt][2]); ps1 += s[nt][2];
            s[nt][3] = exp2f(s[nt][3]); ps1 += s[nt][3];
        }
        l0 += ps0;
        l1 += ps1;

        // ---- O += P @ V^T (P single fp16) ----
#pragma unroll
        for (int kt = 0; kt < 8; ++kt) {
            unsigned ah[4];
            ah[0] = pack2h(s[2 * kt][0],     s[2 * kt][1]);
            ah[1] = pack2h(s[2 * kt][2],     s[2 * kt][3]);
            ah[2] = pack2h(s[2 * kt + 1][0], s[2 * kt + 1][1]);
            ah[3] = pack2h(s[2 * kt + 1][2], s[2 * kt + 1][3]);
            const unsigned cb = (kt * 32 + cbB) ^ mskB;
#pragma unroll
            for (int dt = 0; dt < 8; ++dt) {
                unsigned bv[4];
                LDSM4(bv[0], bv[1], bv[2], bv[3], vbuf + rowB256 + dt * 4096 + cb);
                MMA16816(o[2 * dt],     ah, bv[0], bv[1]);
                MMA16816(o[2 * dt + 1], ah, bv[2], bv[3]);
            }
        }

        __syncthreads();
        if (j + 2 < NB) {
            const unsigned kb2 = sK + (j & 1) * 32768;
            const unsigned vb2 = sV + (j & 1) * 32768;
            fa_load(kb2, Kh + (long long)(j + 2) * 128 * HD, HD, tid);
            fa_load(vb2, Vt + (j + 2) * 128, LEN, tid);
            CP_COMMIT();
        }
    }

    // ---- epilogue: normalize, store fp16 O [L, H*D] ----
    l0 += __shfl_xor_sync(0xffffffffu, l0, 1);
    l0 += __shfl_xor_sync(0xffffffffu, l0, 2);
    l1 += __shfl_xor_sync(0xffffffffu, l1, 1);
    l1 += __shfl_xor_sync(0xffffffffu, l1, 2);
    const float inv0 = 1.0f / l0;
    const float inv1 = 1.0f / l1;

    const int r0g = qb * 128 + q0 + (lane >> 2);
#pragma unroll
    for (int nt = 0; nt < 16; ++nt) {
        const int d = nt * 8 + (lane & 3) * 2;
        const size_t i0 = (size_t)r0g * DIM + h * HD + d;
        const size_t i1 = i0 + (size_t)8 * DIM;
        *reinterpret_cast<unsigned*>(&g_oh[i0]) =
            pack2h(o[nt][0] * inv0, o[nt][1] * inv0);
        *reinterpret_cast<unsigned*>(&g_oh[i1]) =
            pack2h(o[nt][2] * inv1, o[nt][3] * inv1);
    }
}

// ---------------- round x / w_qkv / w_proj to fp16 ----------------
#define SEG_X  (LEN * DIM / 4)
#define SEG_WQ (3 * DIM * DIM / 4)
#define SEG_WP (DIM * DIM / 4)
__global__ void split_inputs(const float* __restrict__ x,
                             const float* __restrict__ wq,
                             const float* __restrict__ wp)
{
    const int i = blockIdx.x * blockDim.x + threadIdx.x;
    if (i < SEG_X) {
        float4 v = reinterpret_cast<const float4*>(x)[i];
        reinterpret_cast<uint2*>(g_xh)[i] =
            make_uint2(pack2h(v.x, v.y), pack2h(v.z, v.w));
    } else if (i < SEG_X + SEG_WQ) {
        const int j = i - SEG_X;
        float4 v = reinterpret_cast<const float4*>(wq)[j];
        reinterpret_cast<uint2*>(g_wqh)[j] =
            make_uint2(pack2h(v.x, v.y), pack2h(v.z, v.w));
    } else if (i < SEG_X + SEG_WQ + SEG_WP) {
        const int j = i - SEG_X - SEG_WQ;
        float4 v = reinterpret_cast<const float4*>(wp)[j];
        reinterpret_cast<uint2*>(g_wph)[j] =
            make_uint2(pack2h(v.x, v.y), pack2h(v.z, v.w));
    }
}

// ---------------- QK RMSNorm + RoPE + V transpose (fp16 qkv input) ------------
__global__ void qknorm_rope(const float* __restrict__ pe,
                            const float* __restrict__ qs,
                            const float* __restrict__ ks)
{
    const int l = blockIdx.x;
    const int h = blockIdx.y;
    const int d = threadIdx.x;

    const __half* base = g_qkv + (size_t)l * (3 * DIM) + h * HD;
    float q = __half2float(base[d]);
    float k = __half2float(base[DIM + d]);
    float v = __half2float(base[2 * DIM + d]);

    float sq = q * q, sk = k * k;
#pragma unroll
    for (int o = 16; o; o >>= 1) {
        sq += __shfl_xor_sync(0xffffffffu, sq, o);
        sk += __shfl_xor_sync(0xffffffffu, sk, o);
    }
    __shared__ float rq[4], rk[4];
    const int w = d >> 5;
    if ((d & 31) == 0) { rq[w] = sq; rk[w] = sk; }
    __syncthreads();
    sq = rq[0] + rq[1] + rq[2] + rq[3];
    sk = rk[0] + rk[1] + rk[2] + rk[3];

    const float rrq = rsqrtf(sq * (1.0f / HD) + 1e-6f);
    const float rrk = rsqrtf(sk * (1.0f / HD) + 1e-6f);
    float qn = q * rrq * qs[d];
    float kn = k * rrk * ks[d];

    const float qp = __shfl_xor_sync(0xffffffffu, qn, 1);
    const float kp = __shfl_xor_sync(0xffffffffu, kn, 1);
    const int j = d >> 1, a = d & 1;
    const float* p = pe + (size_t)l * (HD / 2) * 4 + j * 4 + a * 2;
    const float q0 = a ? qp : qn, q1 = a ? qn : qp;
    const float k0 = a ? kp : kn, k1 = a ? kn : kp;
    const float qr = (p[0] * q0 + p[1] * q1) * (SCALE * LOG2E);
    const float kr = p[0] * k0 + p[1] * k1;

    const size_t idx = ((size_t)h * LEN + l) * HD + d;
    g_qh[idx] = __float2half_rn(qr);
    g_kh[idx] = __float2half_rn(kr);
    g_vth[((size_t)h * HD + d) * LEN + l] = __float2half_rn(v);
}

// ---------------- launch ----------------
extern "C" void kernel_launch(void* const* d_in, const int* in_sizes, int n_in,
                              void* d_out, int out_size)
{
    const float* x      = (const float*)d_in[0];
    const float* pe     = (const float*)d_in[1];
    const float* w_qkv  = (const float*)d_in[2];
    const float* q_sc   = (const float*)d_in[3];
    const float* k_sc   = (const float*)d_in[4];
    const float* w_proj = (const float*)d_in[5];
    const float* b_proj = (const float*)d_in[6];
    float* out = (float*)d_out;

    __half *p_qkv, *p_xh, *p_wqh, *p_wph, *p_oh;
    cudaGetSymbolAddress((void**)&p_qkv, g_qkv);
    cudaGetSymbolAddress((void**)&p_xh,  g_xh);
    cudaGetSymbolAddress((void**)&p_wqh, g_wqh);
    cudaGetSymbolAddress((void**)&p_wph, g_wph);
    cudaGetSymbolAddress((void**)&p_oh,  g_oh);

    cudaFuncSetAttribute((const void*)gemm_nt_h2<256, 64, __half>,
                         cudaFuncAttributeMaxDynamicSharedMemorySize, GSMEM_SINGLE);
    cudaFuncSetAttribute((const void*)gemm_nt_h2<256, 64, float>,
                         cudaFuncAttributeMaxDynamicSharedMemorySize, GSMEM_SINGLE);
    cudaFuncSetAttribute((const void*)flash_attn,
                         cudaFuncAttributeMaxDynamicSharedMemorySize, FA_SMEM);

    // 0) round x, weights to fp16
    {
        const int total = SEG_X + SEG_WQ + SEG_WP;
        split_inputs<<<(total + 255) / 256, 256>>>(x, w_qkv, w_proj);
    }

    // 1) QKV = x @ w_qkv^T : [2048, 6144] fp16 output
    gemm_nt_h2<256, 64, __half><<<dim3(6144 / 256, 2048 / 128, 1), 256, GSMEM_SINGLE>>>(
        p_xh, p_wqh, p_qkv, 2048, 2048, 2048, 6144, 1.0f, nullptr);

    // 2) QK RMSNorm + RoPE + V transpose (SCALE*log2e folded into Q)
    qknorm_rope<<<dim3(LEN, NH), HD>>>(pe, q_sc, k_sc);

    // 3) fused attention (no-max softmax, exp2)
    flash_attn<<<dim3(LEN / 128, NH), 256, FA_SMEM>>>();

    // 4) out = O @ w_proj^T + b_proj : [2048, 2048] fp32
    gemm_nt_h2<256, 64, float><<<dim3(2048 / 256, 2048 / 128, 1), 256, GSMEM_SINGLE>>>(
        p_oh, p_wph, out, 2048, 2048, 2048, 2048, 1.0f, b_proj);
}